// round 4
// baseline (speedup 1.0000x reference)
#include <cuda_runtime.h>
#include <cuda_bf16.h>

#define NN 50000
#define EE 800000
#define ETOT (EE + NN)
#define GG 128
#define NEG_SLOPE 0.2f
#define RB 49   // ceil(NN/1024)

typedef unsigned long long ull;

union F4U { float4 f; ull u[2]; };
union F2U { float2 f; ull u; };
union BF8 { __nv_bfloat162 b[4]; uint4 u; };

__device__ __forceinline__ ull fma2(ull a, ull b, ull c) {
    ull d; asm("fma.rn.f32x2 %0,%1,%2,%3;" : "=l"(d) : "l"(a), "l"(b), "l"(c)); return d;
}
__device__ __forceinline__ ull add2(ull a, ull b) {
    ull d; asm("add.rn.f32x2 %0,%1,%2;" : "=l"(d) : "l"(a), "l"(b)); return d;
}
__device__ __forceinline__ ull pack2(float x) {
    F2U t; t.f = make_float2(x, x); return t.u;
}
__device__ __forceinline__ float2 unpack2(ull v) { F2U t; t.u = v; return t.f; }

// ---------------- scratch ----------------
__device__ float g_x1[NN * 16];
__device__ float g_x2[NN * 32];
__device__ float g_x3[NN * 128];
__device__ float g_x4[NN * 256];
__device__ float g_h [NN * 32];                 // GCN pre-agg features (fp32)
__device__ __nv_bfloat16 g_hb[NN * 256];        // GAT pre-agg features (bf16)
__device__ float g_asrc[NN * 8];
__device__ float g_adst[NN * 8];
__device__ float g_s[NN * 8];
__device__ float g_ex[(size_t)ETOT * 8];
__device__ float g_dinv[NN];
__device__ int   g_counts[NN];
__device__ int   g_bsum[RB];
__device__ int   g_rowptr[NN + 1];
__device__ int   g_csr_src[ETOT];
__device__ int   g_gstart[GG + 1];
__device__ float g_pool[GG * 432];

// ---------------- CSR build ----------------
__global__ void count_edges_kernel(const int* __restrict__ ei, int* __restrict__ counts) {
    int e = blockIdx.x * blockDim.x + threadIdx.x;
    if (e >= ETOT) return;
    int dst = (e < EE) ? ei[EE + e] : (e - EE);
    atomicAdd(&counts[dst], 1);
}

__global__ void scan_reduce_kernel(const int* __restrict__ counts, int* __restrict__ bsum) {
    __shared__ int ws[32];
    int i = blockIdx.x * 1024 + threadIdx.x;
    int v = (i < NN) ? counts[i] : 0;
    int lane = threadIdx.x & 31, w = threadIdx.x >> 5;
#pragma unroll
    for (int o = 16; o; o >>= 1) v += __shfl_xor_sync(0xffffffffu, v, o);
    if (lane == 0) ws[w] = v;
    __syncthreads();
    if (w == 0) {
        int s = ws[lane];
#pragma unroll
        for (int o = 16; o; o >>= 1) s += __shfl_xor_sync(0xffffffffu, s, o);
        if (lane == 0) bsum[blockIdx.x] = s;
    }
}

__global__ void scan_offsets_kernel(int* __restrict__ bsum) {
    __shared__ int ws[2];
    int t = threadIdx.x;   // 64 threads
    int own = (t < RB) ? bsum[t] : 0;
    int v = own;
    int lane = t & 31, w = t >> 5;
#pragma unroll
    for (int o = 1; o < 32; o <<= 1) {
        int u = __shfl_up_sync(0xffffffffu, v, o);
        if (lane >= o) v += u;
    }
    if (lane == 31) ws[w] = v;
    __syncthreads();
    if (w == 1) v += ws[0];
    if (t < RB) bsum[t] = v - own;   // exclusive
}

__global__ void scan_apply_kernel(int* __restrict__ counts, const int* __restrict__ bsum,
                                  int* __restrict__ rowptr, float* __restrict__ dinv) {
    __shared__ int ws[32];
    int i = blockIdx.x * 1024 + threadIdx.x;
    int cnt = (i < NN) ? counts[i] : 0;
    int lane = threadIdx.x & 31, w = threadIdx.x >> 5;
    int v = cnt;
#pragma unroll
    for (int o = 1; o < 32; o <<= 1) {
        int u = __shfl_up_sync(0xffffffffu, v, o);
        if (lane >= o) v += u;
    }
    if (lane == 31) ws[w] = v;
    __syncthreads();
    if (w == 0) {
        int s = ws[lane];
#pragma unroll
        for (int o = 1; o < 32; o <<= 1) {
            int u = __shfl_up_sync(0xffffffffu, s, o);
            if (lane >= o) s += u;
        }
        ws[lane] = s;
    }
    __syncthreads();
    int incl = v + (w ? ws[w - 1] : 0) + bsum[blockIdx.x];
    if (i < NN) {
        rowptr[i + 1] = incl;
        counts[i] = incl - cnt;
        dinv[i] = rsqrtf((float)(cnt > 0 ? cnt : 1));
    }
    if (i == 0) rowptr[0] = 0;
}

__global__ void fill_csr_kernel(const int* __restrict__ ei, int* __restrict__ cursor,
                                int* __restrict__ csr) {
    int e = blockIdx.x * blockDim.x + threadIdx.x;
    if (e >= ETOT) return;
    int src, dst;
    if (e < EE) { src = ei[e]; dst = ei[EE + e]; }
    else        { src = dst = e - EE; }
    int pos = atomicAdd(&cursor[dst], 1);
    csr[pos] = src;
}

__global__ void gstart_kernel(const int* __restrict__ batch, int* __restrict__ gstart) {
    int n = blockIdx.x * blockDim.x + threadIdx.x;
    if (n >= NN) return;
    int b = batch[n];
    if (n == 0) { for (int g = 0; g <= b; g++) gstart[g] = 0; }
    else {
        int pb = batch[n - 1];
        for (int g = pb + 1; g <= b; g++) gstart[g] = n;
    }
    if (n == NN - 1) { for (int g = b + 1; g <= GG; g++) gstart[g] = NN; }
}

// ---------------- small GEMM (M=16/32) ----------------
template<int K, int M>
__global__ void gemm_small_kernel(const float* __restrict__ X, const float* __restrict__ W,
                                  float* __restrict__ Y) {
    constexpr int CT = M;
    constexpr int KC = (K < 64) ? K : 64;
    constexpr int TX = CT / 4;
    constexpr int NT = TX * 16;
    constexpr int RP = 68;
    __shared__ float Xs[KC * RP];
    __shared__ float Ws[KC * CT];
    int row0 = blockIdx.x * 64;
    int tid = threadIdx.y * TX + threadIdx.x;
    float acc[4][4] = {};
    for (int k0 = 0; k0 < K; k0 += KC) {
        for (int idx = tid; idx < 64 * KC; idx += NT) {
            int r = idx / KC, k = idx % KC;
            int gr = row0 + r;
            Xs[k * RP + r] = (gr < NN) ? X[gr * K + k0 + k] : 0.f;
        }
        for (int idx = tid; idx < KC * CT; idx += NT) {
            int k = idx / CT, c = idx % CT;
            Ws[k * CT + c] = W[(k0 + k) * M + c];
        }
        __syncthreads();
#pragma unroll 8
        for (int k = 0; k < KC; k++) {
            float4 xv = *(const float4*)&Xs[k * RP + 4 * threadIdx.y];
            float4 wv = *(const float4*)&Ws[k * CT + 4 * threadIdx.x];
            float xa[4] = {xv.x, xv.y, xv.z, xv.w};
            float wa[4] = {wv.x, wv.y, wv.z, wv.w};
#pragma unroll
            for (int i = 0; i < 4; i++)
#pragma unroll
                for (int j = 0; j < 4; j++)
                    acc[i][j] += xa[i] * wa[j];
        }
        __syncthreads();
    }
#pragma unroll
    for (int i = 0; i < 4; i++) {
        int r = row0 + 4 * threadIdx.y + i;
        if (r < NN) {
            float4 o = make_float4(acc[i][0], acc[i][1], acc[i][2], acc[i][3]);
            *(float4*)&Y[r * M + 4 * threadIdx.x] = o;
        }
    }
}

// ---------------- big GEMM: bf16 output + fused attention coefficients ----------------
template<int K, int M>
__global__ __launch_bounds__(128) void gemm_big_kernel(
        const float* __restrict__ X, const float* __restrict__ W,
        __nv_bfloat16* __restrict__ Yb,
        const float* __restrict__ att_s, const float* __restrict__ att_d,
        float* __restrict__ asrc, float* __restrict__ adst) {
    constexpr int KC = (K < 32) ? K : 32;
    constexpr int RP = 132;
    constexpr int H = M / 32;
    __shared__ float Xs[KC * RP];
    __shared__ ull Ws2[KC * 64];                 // W values pre-duplicated as f32x2
    int tx = threadIdx.x, ty = threadIdx.y;      // (8,16)
    int tid = ty * 8 + tx;
    int row0 = blockIdx.x * 128;
    int c0 = blockIdx.y * 64;
    ull acc[4][8];
#pragma unroll
    for (int p = 0; p < 4; p++)
#pragma unroll
        for (int j = 0; j < 8; j++) acc[p][j] = 0ull;

    for (int k0 = 0; k0 < K; k0 += KC) {
        for (int idx = tid; idx < 128 * (KC / 4); idx += 128) {
            int r = idx / (KC / 4);
            int k4 = (idx % (KC / 4)) * 4;
            int gr = row0 + r;
            float4 v = make_float4(0.f, 0.f, 0.f, 0.f);
            if (gr < NN) v = *(const float4*)&X[gr * K + k0 + k4];
            Xs[(k4 + 0) * RP + r] = v.x;
            Xs[(k4 + 1) * RP + r] = v.y;
            Xs[(k4 + 2) * RP + r] = v.z;
            Xs[(k4 + 3) * RP + r] = v.w;
        }
        for (int idx = tid; idx < KC * 16; idx += 128) {
            int k = idx / 16;
            int c4 = (idx % 16) * 4;
            float4 wv = *(const float4*)&W[(k0 + k) * M + c0 + c4];
            Ws2[k * 64 + c4 + 0] = pack2(wv.x);
            Ws2[k * 64 + c4 + 1] = pack2(wv.y);
            Ws2[k * 64 + c4 + 2] = pack2(wv.z);
            Ws2[k * 64 + c4 + 3] = pack2(wv.w);
        }
        __syncthreads();
#pragma unroll 8
        for (int k = 0; k < KC; k++) {
            const float* xr = &Xs[k * RP + 8 * ty];
            F4U xa, xb;
            xa.f = *(const float4*)xr;
            xb.f = *(const float4*)(xr + 4);
            ull x2[4] = {xa.u[0], xa.u[1], xb.u[0], xb.u[1]};
            const ull* wr = &Ws2[k * 64 + 8 * tx];
            ull w2[8];
#pragma unroll
            for (int j = 0; j < 8; j++) w2[j] = wr[j];
#pragma unroll
            for (int p = 0; p < 4; p++)
#pragma unroll
                for (int j = 0; j < 8; j++)
                    acc[p][j] = fma2(x2[p], w2[j], acc[p][j]);
        }
        __syncthreads();
    }
    // store Y as bf16
#pragma unroll
    for (int p = 0; p < 4; p++) {
        float rlo[8], rhi[8];
#pragma unroll
        for (int j = 0; j < 8; j++) {
            float2 t = unpack2(acc[p][j]);
            rlo[j] = t.x; rhi[j] = t.y;
        }
        int r = row0 + 8 * ty + 2 * p;
        if (r < NN) {
            BF8 o;
#pragma unroll
            for (int q = 0; q < 4; q++)
                o.b[q] = __float22bfloat162_rn(make_float2(rlo[2 * q], rlo[2 * q + 1]));
            *(uint4*)&Yb[(size_t)r * M + c0 + 8 * tx] = o.u;
        }
        if (r + 1 < NN) {
            BF8 o;
#pragma unroll
            for (int q = 0; q < 4; q++)
                o.b[q] = __float22bfloat162_rn(make_float2(rhi[2 * q], rhi[2 * q + 1]));
            *(uint4*)&Yb[(size_t)(r + 1) * M + c0 + 8 * tx] = o.u;
        }
    }
    // fused attention coefficients (exact fp32 from registers)
    {
        int head = (c0 >> 5) + (tx >> 2);
        int cbase = (8 * tx) & 31;
        ull asv[8], adv[8];
#pragma unroll
        for (int j = 0; j < 8; j++) {
            asv[j] = pack2(att_s[head * 32 + cbase + j]);
            adv[j] = pack2(att_d[head * 32 + cbase + j]);
        }
#pragma unroll
        for (int p = 0; p < 4; p++) {
            ull s2 = 0ull, d2 = 0ull;
#pragma unroll
            for (int j = 0; j < 8; j++) {
                s2 = fma2(acc[p][j], asv[j], s2);
                d2 = fma2(acc[p][j], adv[j], d2);
            }
            s2 = add2(s2, __shfl_xor_sync(0xffffffffu, s2, 1));
            s2 = add2(s2, __shfl_xor_sync(0xffffffffu, s2, 2));
            d2 = add2(d2, __shfl_xor_sync(0xffffffffu, d2, 1));
            d2 = add2(d2, __shfl_xor_sync(0xffffffffu, d2, 2));
            if ((tx & 3) == 0) {
                float2 sv = unpack2(s2), dv = unpack2(d2);
                int r = row0 + 8 * ty + 2 * p;
                if (r < NN)     { asrc[r * H + head] = sv.x; adst[r * H + head] = dv.x; }
                if (r + 1 < NN) { asrc[(r + 1) * H + head] = sv.y; adst[(r + 1) * H + head] = dv.y; }
            }
        }
    }
}

// ---------------- GCN aggregate ----------------
template<int C>
__global__ void gcn_agg_kernel(const float* __restrict__ h, const float* __restrict__ dinv,
                               const int* __restrict__ rowptr, const int* __restrict__ csr,
                               const float* __restrict__ bias, float* __restrict__ out) {
    constexpr int TPN = C / 4;
    int gtid = blockIdx.x * blockDim.x + threadIdx.x;
    int n = gtid / TPN;
    int ch = 4 * (gtid % TPN);
    if (n >= NN) return;
    int r0 = rowptr[n], r1 = rowptr[n + 1];
    const float* hb = h + ch;
    ull a0 = 0ull, a1 = 0ull;
    for (int j = r0; j < r1; j++) {
        int s = csr[j];
        ull dv2 = pack2(dinv[s]);
        F4U hv; hv.f = *(const float4*)(hb + s * C);
        a0 = fma2(hv.u[0], dv2, a0);
        a1 = fma2(hv.u[1], dv2, a1);
    }
    float dn = dinv[n];
    float2 r01 = unpack2(a0), r23 = unpack2(a1);
    float4 b = *(const float4*)&bias[ch];
    float4 o;
    o.x = fmaxf(r01.x * dn + b.x, 0.f);
    o.y = fmaxf(r01.y * dn + b.y, 0.f);
    o.z = fmaxf(r23.x * dn + b.z, 0.f);
    o.w = fmaxf(r23.y * dn + b.w, 0.f);
    *(float4*)&out[n * C + ch] = o;
}

// ---------------- GAT: max + sum(exp), cache exp(e-m) ----------------
template<int H>
__global__ void gat_maxsum_kernel(const float* __restrict__ asrc, const float* __restrict__ adst,
                                  const int* __restrict__ rowptr, const int* __restrict__ csr,
                                  float* __restrict__ sArr, float* __restrict__ ex) {
    int warp = (blockIdx.x * blockDim.x + threadIdx.x) >> 5;
    int lane = threadIdx.x & 31;
    int n = warp;
    if (n >= NN) return;
    float ad[H];
#pragma unroll
    for (int q = 0; q < H / 4; q++) {
        float4 v = *(const float4*)&adst[n * H + 4 * q];
        ad[4 * q + 0] = v.x; ad[4 * q + 1] = v.y; ad[4 * q + 2] = v.z; ad[4 * q + 3] = v.w;
    }
    int r0 = rowptr[n], r1 = rowptr[n + 1];
    float mx[H];
#pragma unroll
    for (int hd = 0; hd < H; hd++) mx[hd] = -1e30f;
    for (int j = r0 + lane; j < r1; j += 32) {
        int s = csr[j];
        float as[H];
#pragma unroll
        for (int q = 0; q < H / 4; q++) {
            float4 v = *(const float4*)&asrc[s * H + 4 * q];
            as[4 * q + 0] = v.x; as[4 * q + 1] = v.y; as[4 * q + 2] = v.z; as[4 * q + 3] = v.w;
        }
#pragma unroll
        for (int hd = 0; hd < H; hd++) {
            float e = as[hd] + ad[hd];
            e = fmaxf(e, NEG_SLOPE * e);
            mx[hd] = fmaxf(mx[hd], e);
        }
    }
#pragma unroll
    for (int hd = 0; hd < H; hd++)
#pragma unroll
        for (int o = 16; o; o >>= 1) mx[hd] = fmaxf(mx[hd], __shfl_xor_sync(0xffffffffu, mx[hd], o));
    float sm[H];
#pragma unroll
    for (int hd = 0; hd < H; hd++) sm[hd] = 0.f;
    for (int j = r0 + lane; j < r1; j += 32) {
        int s = csr[j];
        float as[H];
#pragma unroll
        for (int q = 0; q < H / 4; q++) {
            float4 v = *(const float4*)&asrc[s * H + 4 * q];
            as[4 * q + 0] = v.x; as[4 * q + 1] = v.y; as[4 * q + 2] = v.z; as[4 * q + 3] = v.w;
        }
        float exv[H];
#pragma unroll
        for (int hd = 0; hd < H; hd++) {
            float e = as[hd] + ad[hd];
            e = fmaxf(e, NEG_SLOPE * e);
            float xv = __expf(e - mx[hd]);
            exv[hd] = xv;
            sm[hd] += xv;
        }
#pragma unroll
        for (int q = 0; q < H / 4; q++)
            *(float4*)&ex[(size_t)j * H + 4 * q] =
                make_float4(exv[4 * q + 0], exv[4 * q + 1], exv[4 * q + 2], exv[4 * q + 3]);
    }
#pragma unroll
    for (int hd = 0; hd < H; hd++)
#pragma unroll
        for (int o = 16; o; o >>= 1) sm[hd] += __shfl_xor_sync(0xffffffffu, sm[hd], o);
    if (lane == 0) {
#pragma unroll
        for (int hd = 0; hd < H; hd++) sArr[n * H + hd] = sm[hd];
    }
}

// ---------------- GAT aggregation: bf16 h gather ----------------
template<int H>
__global__ __launch_bounds__(128) void gat_agg_kernel(
        const __nv_bfloat16* __restrict__ h, const float* __restrict__ ex,
        const float* __restrict__ sArr, const int* __restrict__ rowptr,
        const int* __restrict__ csr, const float* __restrict__ bias,
        float* __restrict__ out) {
    constexpr int HC = H * 32;
    constexpr int TPN = HC / 4;
    constexpr int NPB = 128 / TPN;
    constexpr int CH = 32;
    __shared__ float2 al_sh[NPB][CH * H];
    __shared__ int off_sh[NPB][CH];
    __shared__ float inv_sh[NPB][H];
    __shared__ int r0_sh[NPB];
    __shared__ int cnt_sh[NPB];
    __shared__ int mx_sh;

    int tid = threadIdx.x;
    int g = tid / TPN, tg = tid % TPN;
    int n = blockIdx.x * NPB + g;
    if (tid == 0) mx_sh = 0;
    if (tg < H) inv_sh[g][tg] = 1.f / sArr[n * H + tg];
    if (tg == 0) {
        int r0 = rowptr[n], r1 = rowptr[n + 1];
        r0_sh[g] = r0;
        cnt_sh[g] = r1 - r0;
    }
    __syncthreads();
    if (tg == 0) atomicMax(&mx_sh, cnt_sh[g]);
    __syncthreads();
    int cnt = cnt_sh[g], r0 = r0_sh[g];
    int nch = (mx_sh + CH - 1) / CH;
    int ch0 = 4 * tg;
    int hd = tg >> 3;
    const __nv_bfloat16* hb = h + ch0;
    ull a0 = 0ull, a1 = 0ull;

    for (int c = 0; c < nch; c++) {
        int base = c * CH;
        int cc = min(CH, cnt - base);
#pragma unroll
        for (int it = 0; it < CH * H / TPN; it++) {
            int task = tg + it * TPN;
            int e = task / H;
            int hh = task - e * H;
            if (e < cc) {
                int j = r0 + base + e;
                float a = ex[(size_t)j * H + hh] * inv_sh[g][hh];
                al_sh[g][task] = make_float2(a, a);
                if (hh == 0) off_sh[g][e] = csr[j] * HC;
            }
        }
        __syncthreads();
        int e = 0;
        for (; e + 4 <= cc; e += 4) {
            int o0 = off_sh[g][e], o1 = off_sh[g][e + 1], o2 = off_sh[g][e + 2], o3 = off_sh[g][e + 3];
            F2U A0, A1, A2, A3;
            A0.f = al_sh[g][(e + 0) * H + hd];
            A1.f = al_sh[g][(e + 1) * H + hd];
            A2.f = al_sh[g][(e + 2) * H + hd];
            A3.f = al_sh[g][(e + 3) * H + hd];
            uint2 v0 = *(const uint2*)(hb + o0);
            uint2 v1 = *(const uint2*)(hb + o1);
            uint2 v2 = *(const uint2*)(hb + o2);
            uint2 v3 = *(const uint2*)(hb + o3);
            F2U f;
            f.f = __bfloat1622float2(*(__nv_bfloat162*)&v0.x); a0 = fma2(f.u, A0.u, a0);
            f.f = __bfloat1622float2(*(__nv_bfloat162*)&v0.y); a1 = fma2(f.u, A0.u, a1);
            f.f = __bfloat1622float2(*(__nv_bfloat162*)&v1.x); a0 = fma2(f.u, A1.u, a0);
            f.f = __bfloat1622float2(*(__nv_bfloat162*)&v1.y); a1 = fma2(f.u, A1.u, a1);
            f.f = __bfloat1622float2(*(__nv_bfloat162*)&v2.x); a0 = fma2(f.u, A2.u, a0);
            f.f = __bfloat1622float2(*(__nv_bfloat162*)&v2.y); a1 = fma2(f.u, A2.u, a1);
            f.f = __bfloat1622float2(*(__nv_bfloat162*)&v3.x); a0 = fma2(f.u, A3.u, a0);
            f.f = __bfloat1622float2(*(__nv_bfloat162*)&v3.y); a1 = fma2(f.u, A3.u, a1);
        }
        for (; e < cc; e++) {
            int o = off_sh[g][e];
            F2U A; A.f = al_sh[g][e * H + hd];
            uint2 v = *(const uint2*)(hb + o);
            F2U f;
            f.f = __bfloat1622float2(*(__nv_bfloat162*)&v.x); a0 = fma2(f.u, A.u, a0);
            f.f = __bfloat1622float2(*(__nv_bfloat162*)&v.y); a1 = fma2(f.u, A.u, a1);
        }
        __syncthreads();
    }
    float2 r01 = unpack2(a0), r23 = unpack2(a1);
    float4 b = *(const float4*)&bias[ch0];
    float4 o;
    o.x = fmaxf(r01.x + b.x, 0.f);
    o.y = fmaxf(r01.y + b.y, 0.f);
    o.z = fmaxf(r23.x + b.z, 0.f);
    o.w = fmaxf(r23.y + b.w, 0.f);
    *(float4*)&out[n * HC + ch0] = o;
}

// ---------------- pooling partials per layer ----------------
template<int NF4>
__global__ void pool_part_kernel(const float* __restrict__ src, int obase, int qy_total,
                                 const int* __restrict__ gstart, float* __restrict__ pool) {
    constexpr int SPB = 128 / NF4;
    int g = blockIdx.x;
    int q = blockIdx.y * SPB + threadIdx.x / NF4;
    int f = threadIdx.x % NF4;
    int slices = qy_total * SPB;
    int s = gstart[g], e = gstart[g + 1];
    int len = e - s;
    int n0 = s + (int)((long long)len * q / slices);
    int n1 = s + (int)((long long)len * (q + 1) / slices);
    ull a0 = 0ull, a1 = 0ull;
    int stride = NF4 * 4;
    for (int n = n0; n < n1; n++) {
        F4U v; v.f = *(const float4*)&src[(size_t)n * stride + 4 * f];
        a0 = add2(a0, v.u[0]);
        a1 = add2(a1, v.u[1]);
    }
    float2 r01 = unpack2(a0), r23 = unpack2(a1);
    float* dst = &pool[g * 432 + obase + 4 * f];
    atomicAdd(dst + 0, r01.x);
    atomicAdd(dst + 1, r01.y);
    atomicAdd(dst + 2, r23.x);
    atomicAdd(dst + 3, r23.y);
}

// ---------------- final MLP ----------------
__global__ void fc_kernel(const float* __restrict__ pool, const int* __restrict__ gstart,
                          const float* __restrict__ W1, const float* __restrict__ b1,
                          const float* __restrict__ W2, const float* __restrict__ b2,
                          float* __restrict__ out) {
    int g = blockIdx.x, t = threadIdx.x;
    __shared__ float xp[432];
    __shared__ float ws[4];
    float cntf = (float)(gstart[g + 1] - gstart[g]);
    float invc = 1.f / fmaxf(cntf, 1.f);
    for (int i = t; i < 432; i += 128) xp[i] = pool[g * 432 + i] * invc;
    __syncthreads();
    float acc = b1[t];
    for (int i = 0; i < 432; i++) acc += xp[i] * W1[i * 128 + t];
    acc = fmaxf(acc, 0.f);
    float v = acc * W2[t];
#pragma unroll
    for (int o = 16; o; o >>= 1) v += __shfl_xor_sync(0xffffffffu, v, o);
    if ((t & 31) == 0) ws[t >> 5] = v;
    __syncthreads();
    if (t == 0) out[g] = ws[0] + ws[1] + ws[2] + ws[3] + b2[0];
}

// ---------------- launch ----------------
extern "C" void kernel_launch(void* const* d_in, const int* in_sizes, int n_in,
                              void* d_out, int out_size) {
    const float* x    = (const float*)d_in[0];
    const int*   ei   = (const int*)d_in[1];
    const int*   batch= (const int*)d_in[2];
    const float* W1   = (const float*)d_in[3];
    const float* b1   = (const float*)d_in[4];
    const float* W2   = (const float*)d_in[5];
    const float* b2   = (const float*)d_in[6];
    const float* W3   = (const float*)d_in[7];
    const float* as3  = (const float*)d_in[8];
    const float* ad3  = (const float*)d_in[9];
    const float* b3   = (const float*)d_in[10];
    const float* W4   = (const float*)d_in[11];
    const float* as4  = (const float*)d_in[12];
    const float* ad4  = (const float*)d_in[13];
    const float* b4   = (const float*)d_in[14];
    const float* Wfc1 = (const float*)d_in[15];
    const float* bfc1 = (const float*)d_in[16];
    const float* Wfc2 = (const float*)d_in[17];
    const float* bfc2 = (const float*)d_in[18];
    float* out = (float*)d_out;

    static float *p_x1 = nullptr, *p_x2, *p_x3, *p_x4, *p_h, *p_asrc, *p_adst, *p_s,
                 *p_ex, *p_dinv, *p_pool;
    static __nv_bfloat16* p_hb;
    static int *p_counts, *p_bsum, *p_rowptr, *p_csr, *p_gstart;
    static cudaStream_t s1, s2;
    static cudaEvent_t evRoot, evG1, evX1, evX2, evX3, evX4, evFC;
    if (!p_x1) {
        cudaGetSymbolAddress((void**)&p_x1, g_x1);
        cudaGetSymbolAddress((void**)&p_x2, g_x2);
        cudaGetSymbolAddress((void**)&p_x3, g_x3);
        cudaGetSymbolAddress((void**)&p_x4, g_x4);
        cudaGetSymbolAddress((void**)&p_h, g_h);
        cudaGetSymbolAddress((void**)&p_hb, g_hb);
        cudaGetSymbolAddress((void**)&p_asrc, g_asrc);
        cudaGetSymbolAddress((void**)&p_adst, g_adst);
        cudaGetSymbolAddress((void**)&p_s, g_s);
        cudaGetSymbolAddress((void**)&p_ex, g_ex);
        cudaGetSymbolAddress((void**)&p_dinv, g_dinv);
        cudaGetSymbolAddress((void**)&p_pool, g_pool);
        cudaGetSymbolAddress((void**)&p_counts, g_counts);
        cudaGetSymbolAddress((void**)&p_bsum, g_bsum);
        cudaGetSymbolAddress((void**)&p_rowptr, g_rowptr);
        cudaGetSymbolAddress((void**)&p_csr, g_csr_src);
        cudaGetSymbolAddress((void**)&p_gstart, g_gstart);
        cudaStreamCreateWithFlags(&s1, cudaStreamNonBlocking);
        cudaStreamCreateWithFlags(&s2, cudaStreamNonBlocking);
        cudaEventCreateWithFlags(&evRoot, cudaEventDisableTiming);
        cudaEventCreateWithFlags(&evG1, cudaEventDisableTiming);
        cudaEventCreateWithFlags(&evX1, cudaEventDisableTiming);
        cudaEventCreateWithFlags(&evX2, cudaEventDisableTiming);
        cudaEventCreateWithFlags(&evX3, cudaEventDisableTiming);
        cudaEventCreateWithFlags(&evX4, cudaEventDisableTiming);
        cudaEventCreateWithFlags(&evFC, cudaEventDisableTiming);
    }

    // fork
    cudaEventRecord(evRoot, 0);
    cudaStreamWaitEvent(s1, evRoot, 0);
    cudaStreamWaitEvent(s2, evRoot, 0);

    // s0: CSR chain
    cudaMemsetAsync(p_counts, 0, NN * sizeof(int), 0);
    count_edges_kernel<<<(ETOT + 255) / 256, 256>>>(ei, p_counts);
    scan_reduce_kernel<<<RB, 1024>>>(p_counts, p_bsum);
    scan_offsets_kernel<<<1, 64>>>(p_bsum);
    scan_apply_kernel<<<RB, 1024>>>(p_counts, p_bsum, p_rowptr, p_dinv);
    fill_csr_kernel<<<(ETOT + 255) / 256, 256>>>(ei, p_counts, p_csr);

    // s1: gstart + pool init (independent)
    gstart_kernel<<<(NN + 255) / 256, 256, 0, s1>>>(batch, p_gstart);
    cudaMemsetAsync(p_pool, 0, GG * 432 * sizeof(float), s1);

    // s2: GEMM1 (independent of CSR)
    {
        dim3 b(4, 16), g((NN + 63) / 64, 1);
        gemm_small_kernel<128, 16><<<g, b, 0, s2>>>(x, W1, p_h);
        cudaEventRecord(evG1, s2);
    }

    // GCN layer 1 aggregate
    cudaStreamWaitEvent(0, evG1, 0);
    gcn_agg_kernel<16><<<(NN * 4 + 255) / 256, 256>>>(p_h, p_dinv, p_rowptr, p_csr, b1, p_x1);
    cudaEventRecord(evX1, 0);
    cudaStreamWaitEvent(s1, evX1, 0);
    pool_part_kernel<4><<<dim3(GG, 1), 128, 0, s1>>>(p_x1, 0, 1, p_gstart, p_pool);

    // GCN layer 2
    {
        dim3 b(8, 16), g((NN + 63) / 64, 1);
        gemm_small_kernel<16, 32><<<g, b>>>(p_x1, W2, p_h);
    }
    gcn_agg_kernel<32><<<(NN * 8 + 255) / 256, 256>>>(p_h, p_dinv, p_rowptr, p_csr, b2, p_x2);
    cudaEventRecord(evX2, 0);
    cudaStreamWaitEvent(s1, evX2, 0);
    pool_part_kernel<8><<<dim3(GG, 1), 128, 0, s1>>>(p_x2, 16, 1, p_gstart, p_pool);

    // GAT layer 3 (32 -> 4x32)
    {
        dim3 b(8, 16), g((NN + 127) / 128, 2);
        gemm_big_kernel<32, 128><<<g, b>>>(p_x2, W3, p_hb, as3, ad3, p_asrc, p_adst);
    }
    gat_maxsum_kernel<4><<<(NN * 32 + 255) / 256, 256>>>(p_asrc, p_adst, p_rowptr, p_csr, p_s, p_ex);
    gat_agg_kernel<4><<<NN / 4, 128>>>(p_hb, p_ex, p_s, p_rowptr, p_csr, b3, p_x3);
    cudaEventRecord(evX3, 0);
    cudaStreamWaitEvent(s1, evX3, 0);
    pool_part_kernel<32><<<dim3(GG, 2), 128, 0, s1>>>(p_x3, 48, 2, p_gstart, p_pool);

    // GAT layer 4 (128 -> 8x32)
    {
        dim3 b(8, 16), g((NN + 127) / 128, 4);
        gemm_big_kernel<128, 256><<<g, b>>>(p_x3, W4, p_hb, as4, ad4, p_asrc, p_adst);
    }
    gat_maxsum_kernel<8><<<(NN * 32 + 255) / 256, 256>>>(p_asrc, p_adst, p_rowptr, p_csr, p_s, p_ex);
    gat_agg_kernel<8><<<NN / 2, 128>>>(p_hb, p_ex, p_s, p_rowptr, p_csr, b4, p_x4);
    cudaEventRecord(evX4, 0);
    cudaStreamWaitEvent(s1, evX4, 0);
    pool_part_kernel<64><<<dim3(GG, 4), 128, 0, s1>>>(p_x4, 176, 4, p_gstart, p_pool);

    // FC on s1
    fc_kernel<<<GG, 128, 0, s1>>>(p_pool, p_gstart, Wfc1, bfc1, Wfc2, bfc2, out);
    cudaEventRecord(evFC, s1);
    cudaStreamWaitEvent(0, evFC, 0);
}

// round 5
// speedup vs baseline: 1.4244x; 1.4244x over previous
#include <cuda_runtime.h>
#include <cuda_bf16.h>

#define NN 50000
#define EE 800000
#define ETOT (EE + NN)
#define GG 128
#define NEG_SLOPE 0.2f
#define RB 49   // ceil(NN/1024)

typedef unsigned long long ull;

union F4U { float4 f; ull u[2]; };
union F2U { float2 f; ull u; };
union BF8 { __nv_bfloat162 b[4]; uint4 u; };

__device__ __forceinline__ ull fma2(ull a, ull b, ull c) {
    ull d; asm("fma.rn.f32x2 %0,%1,%2,%3;" : "=l"(d) : "l"(a), "l"(b), "l"(c)); return d;
}
__device__ __forceinline__ ull add2(ull a, ull b) {
    ull d; asm("add.rn.f32x2 %0,%1,%2;" : "=l"(d) : "l"(a), "l"(b)); return d;
}
__device__ __forceinline__ ull pack2(float x) {
    F2U t; t.f = make_float2(x, x); return t.u;
}
__device__ __forceinline__ float2 unpack2(ull v) { F2U t; t.u = v; return t.f; }

// ---------------- scratch ----------------
__device__ float g_x1[NN * 16];
__device__ float g_x2[NN * 32];
__device__ float g_x3[NN * 128];
__device__ float g_x4[NN * 256];
__device__ float g_h [NN * 32];                 // GCN pre-agg features (fp32)
__device__ __nv_bfloat16 g_hb[NN * 256];        // GAT pre-agg features (bf16)
__device__ float g_asrc[NN * 8];
__device__ float g_adst[NN * 8];
__device__ float g_s[NN * 8];
__device__ float g_ex[(size_t)ETOT * 8];
__device__ float g_dinv[NN];
__device__ int   g_counts[NN];
__device__ int   g_bsum[RB];
__device__ int   g_rowptr[NN + 1];
__device__ int   g_csr_src[ETOT];
__device__ int   g_gstart[GG + 1];
__device__ float g_pool[GG * 432];

// ---------------- CSR build ----------------
__global__ void count_edges_kernel(const int* __restrict__ ei, int* __restrict__ counts) {
    int e = blockIdx.x * blockDim.x + threadIdx.x;
    if (e >= ETOT) return;
    int dst = (e < EE) ? ei[EE + e] : (e - EE);
    atomicAdd(&counts[dst], 1);
}

__global__ void scan_reduce_kernel(const int* __restrict__ counts, int* __restrict__ bsum) {
    __shared__ int ws[32];
    int i = blockIdx.x * 1024 + threadIdx.x;
    int v = (i < NN) ? counts[i] : 0;
    int lane = threadIdx.x & 31, w = threadIdx.x >> 5;
#pragma unroll
    for (int o = 16; o; o >>= 1) v += __shfl_xor_sync(0xffffffffu, v, o);
    if (lane == 0) ws[w] = v;
    __syncthreads();
    if (w == 0) {
        int s = ws[lane];
#pragma unroll
        for (int o = 16; o; o >>= 1) s += __shfl_xor_sync(0xffffffffu, s, o);
        if (lane == 0) bsum[blockIdx.x] = s;
    }
}

__global__ void scan_offsets_kernel(int* __restrict__ bsum) {
    __shared__ int ws[2];
    int t = threadIdx.x;   // 64 threads
    int own = (t < RB) ? bsum[t] : 0;
    int v = own;
    int lane = t & 31, w = t >> 5;
#pragma unroll
    for (int o = 1; o < 32; o <<= 1) {
        int u = __shfl_up_sync(0xffffffffu, v, o);
        if (lane >= o) v += u;
    }
    if (lane == 31) ws[w] = v;
    __syncthreads();
    if (w == 1) v += ws[0];
    if (t < RB) bsum[t] = v - own;   // exclusive
}

__global__ void scan_apply_kernel(int* __restrict__ counts, const int* __restrict__ bsum,
                                  int* __restrict__ rowptr, float* __restrict__ dinv) {
    __shared__ int ws[32];
    int i = blockIdx.x * 1024 + threadIdx.x;
    int cnt = (i < NN) ? counts[i] : 0;
    int lane = threadIdx.x & 31, w = threadIdx.x >> 5;
    int v = cnt;
#pragma unroll
    for (int o = 1; o < 32; o <<= 1) {
        int u = __shfl_up_sync(0xffffffffu, v, o);
        if (lane >= o) v += u;
    }
    if (lane == 31) ws[w] = v;
    __syncthreads();
    if (w == 0) {
        int s = ws[lane];
#pragma unroll
        for (int o = 1; o < 32; o <<= 1) {
            int u = __shfl_up_sync(0xffffffffu, s, o);
            if (lane >= o) s += u;
        }
        ws[lane] = s;
    }
    __syncthreads();
    int incl = v + (w ? ws[w - 1] : 0) + bsum[blockIdx.x];
    if (i < NN) {
        rowptr[i + 1] = incl;
        counts[i] = incl - cnt;
        dinv[i] = rsqrtf((float)(cnt > 0 ? cnt : 1));
    }
    if (i == 0) rowptr[0] = 0;
}

__global__ void fill_csr_kernel(const int* __restrict__ ei, int* __restrict__ cursor,
                                int* __restrict__ csr) {
    int e = blockIdx.x * blockDim.x + threadIdx.x;
    if (e >= ETOT) return;
    int src, dst;
    if (e < EE) { src = ei[e]; dst = ei[EE + e]; }
    else        { src = dst = e - EE; }
    int pos = atomicAdd(&cursor[dst], 1);
    csr[pos] = src;
}

__global__ void gstart_kernel(const int* __restrict__ batch, int* __restrict__ gstart) {
    int n = blockIdx.x * blockDim.x + threadIdx.x;
    if (n >= NN) return;
    int b = batch[n];
    if (n == 0) { for (int g = 0; g <= b; g++) gstart[g] = 0; }
    else {
        int pb = batch[n - 1];
        for (int g = pb + 1; g <= b; g++) gstart[g] = n;
    }
    if (n == NN - 1) { for (int g = b + 1; g <= GG; g++) gstart[g] = NN; }
}

// ---------------- small GEMM (M=16/32) ----------------
template<int K, int M>
__global__ void gemm_small_kernel(const float* __restrict__ X, const float* __restrict__ W,
                                  float* __restrict__ Y) {
    constexpr int CT = M;
    constexpr int KC = (K < 64) ? K : 64;
    constexpr int TX = CT / 4;
    constexpr int NT = TX * 16;
    constexpr int RP = 68;
    __shared__ float Xs[KC * RP];
    __shared__ float Ws[KC * CT];
    int row0 = blockIdx.x * 64;
    int tid = threadIdx.y * TX + threadIdx.x;
    float acc[4][4] = {};
    for (int k0 = 0; k0 < K; k0 += KC) {
        for (int idx = tid; idx < 64 * KC; idx += NT) {
            int r = idx / KC, k = idx % KC;
            int gr = row0 + r;
            Xs[k * RP + r] = (gr < NN) ? X[gr * K + k0 + k] : 0.f;
        }
        for (int idx = tid; idx < KC * CT; idx += NT) {
            int k = idx / CT, c = idx % CT;
            Ws[k * CT + c] = W[(k0 + k) * M + c];
        }
        __syncthreads();
#pragma unroll 8
        for (int k = 0; k < KC; k++) {
            float4 xv = *(const float4*)&Xs[k * RP + 4 * threadIdx.y];
            float4 wv = *(const float4*)&Ws[k * CT + 4 * threadIdx.x];
            float xa[4] = {xv.x, xv.y, xv.z, xv.w};
            float wa[4] = {wv.x, wv.y, wv.z, wv.w};
#pragma unroll
            for (int i = 0; i < 4; i++)
#pragma unroll
                for (int j = 0; j < 4; j++)
                    acc[i][j] += xa[i] * wa[j];
        }
        __syncthreads();
    }
#pragma unroll
    for (int i = 0; i < 4; i++) {
        int r = row0 + 4 * threadIdx.y + i;
        if (r < NN) {
            float4 o = make_float4(acc[i][0], acc[i][1], acc[i][2], acc[i][3]);
            *(float4*)&Y[r * M + 4 * threadIdx.x] = o;
        }
    }
}

// ---------------- big GEMM: R3 inner loop, bf16 output + fused att coefs ----------------
template<int K, int M>
__global__ __launch_bounds__(128) void gemm_big_kernel(
        const float* __restrict__ X, const float* __restrict__ W,
        __nv_bfloat16* __restrict__ Yb,
        const float* __restrict__ att_s, const float* __restrict__ att_d,
        float* __restrict__ asrc, float* __restrict__ adst) {
    constexpr int KC = (K < 32) ? K : 32;
    constexpr int RP = 132;
    constexpr int H = M / 32;
    __shared__ float Xs[KC * RP];
    __shared__ float Ws[KC * 64];
    int tx = threadIdx.x, ty = threadIdx.y;      // (8,16)
    int tid = ty * 8 + tx;
    int row0 = blockIdx.x * 128;
    int c0 = blockIdx.y * 64;
    ull acc[4][8];
#pragma unroll
    for (int p = 0; p < 4; p++)
#pragma unroll
        for (int j = 0; j < 8; j++) acc[p][j] = 0ull;

    for (int k0 = 0; k0 < K; k0 += KC) {
        for (int idx = tid; idx < 128 * (KC / 4); idx += 128) {
            int r = idx / (KC / 4);
            int k4 = (idx % (KC / 4)) * 4;
            int gr = row0 + r;
            float4 v = make_float4(0.f, 0.f, 0.f, 0.f);
            if (gr < NN) v = *(const float4*)&X[gr * K + k0 + k4];
            Xs[(k4 + 0) * RP + r] = v.x;
            Xs[(k4 + 1) * RP + r] = v.y;
            Xs[(k4 + 2) * RP + r] = v.z;
            Xs[(k4 + 3) * RP + r] = v.w;
        }
        for (int idx = tid; idx < KC * 16; idx += 128) {
            int k = idx / 16;
            int c4 = (idx % 16) * 4;
            *(float4*)&Ws[k * 64 + c4] = *(const float4*)&W[(k0 + k) * M + c0 + c4];
        }
        __syncthreads();
#pragma unroll 8
        for (int k = 0; k < KC; k++) {
            const float* xr = &Xs[k * RP + 8 * ty];
            F4U xa, xb;
            xa.f = *(const float4*)xr;
            xb.f = *(const float4*)(xr + 4);
            ull x2[4] = {xa.u[0], xa.u[1], xb.u[0], xb.u[1]};
            const float* wr = &Ws[k * 64 + 8 * tx];
            float4 wa = *(const float4*)wr;
            float4 wb = *(const float4*)(wr + 4);
            ull w2[8];
            w2[0] = pack2(wa.x); w2[1] = pack2(wa.y); w2[2] = pack2(wa.z); w2[3] = pack2(wa.w);
            w2[4] = pack2(wb.x); w2[5] = pack2(wb.y); w2[6] = pack2(wb.z); w2[7] = pack2(wb.w);
#pragma unroll
            for (int p = 0; p < 4; p++)
#pragma unroll
                for (int j = 0; j < 8; j++)
                    acc[p][j] = fma2(x2[p], w2[j], acc[p][j]);
        }
        __syncthreads();
    }
    // store Y as bf16
#pragma unroll
    for (int p = 0; p < 4; p++) {
        float rlo[8], rhi[8];
#pragma unroll
        for (int j = 0; j < 8; j++) {
            float2 t = unpack2(acc[p][j]);
            rlo[j] = t.x; rhi[j] = t.y;
        }
        int r = row0 + 8 * ty + 2 * p;
        if (r < NN) {
            BF8 o;
#pragma unroll
            for (int q = 0; q < 4; q++)
                o.b[q] = __float22bfloat162_rn(make_float2(rlo[2 * q], rlo[2 * q + 1]));
            *(uint4*)&Yb[(size_t)r * M + c0 + 8 * tx] = o.u;
        }
        if (r + 1 < NN) {
            BF8 o;
#pragma unroll
            for (int q = 0; q < 4; q++)
                o.b[q] = __float22bfloat162_rn(make_float2(rhi[2 * q], rhi[2 * q + 1]));
            *(uint4*)&Yb[(size_t)(r + 1) * M + c0 + 8 * tx] = o.u;
        }
    }
    // fused attention coefficients (exact fp32 from registers)
    {
        int head = (c0 >> 5) + (tx >> 2);
        int cbase = (8 * tx) & 31;
        ull asv[8], adv[8];
#pragma unroll
        for (int j = 0; j < 8; j++) {
            asv[j] = pack2(att_s[head * 32 + cbase + j]);
            adv[j] = pack2(att_d[head * 32 + cbase + j]);
        }
#pragma unroll
        for (int p = 0; p < 4; p++) {
            ull s2 = 0ull, d2 = 0ull;
#pragma unroll
            for (int j = 0; j < 8; j++) {
                s2 = fma2(acc[p][j], asv[j], s2);
                d2 = fma2(acc[p][j], adv[j], d2);
            }
            s2 = add2(s2, __shfl_xor_sync(0xffffffffu, s2, 1));
            s2 = add2(s2, __shfl_xor_sync(0xffffffffu, s2, 2));
            d2 = add2(d2, __shfl_xor_sync(0xffffffffu, d2, 1));
            d2 = add2(d2, __shfl_xor_sync(0xffffffffu, d2, 2));
            if ((tx & 3) == 0) {
                float2 sv = unpack2(s2), dv = unpack2(d2);
                int r = row0 + 8 * ty + 2 * p;
                if (r < NN)     { asrc[r * H + head] = sv.x; adst[r * H + head] = dv.x; }
                if (r + 1 < NN) { asrc[(r + 1) * H + head] = sv.y; adst[(r + 1) * H + head] = dv.y; }
            }
        }
    }
}

// ---------------- GCN aggregate ----------------
template<int C>
__global__ void gcn_agg_kernel(const float* __restrict__ h, const float* __restrict__ dinv,
                               const int* __restrict__ rowptr, const int* __restrict__ csr,
                               const float* __restrict__ bias, float* __restrict__ out) {
    constexpr int TPN = C / 4;
    int gtid = blockIdx.x * blockDim.x + threadIdx.x;
    int n = gtid / TPN;
    int ch = 4 * (gtid % TPN);
    if (n >= NN) return;
    int r0 = rowptr[n], r1 = rowptr[n + 1];
    const float* hb = h + ch;
    ull a0 = 0ull, a1 = 0ull;
    for (int j = r0; j < r1; j++) {
        int s = csr[j];
        ull dv2 = pack2(dinv[s]);
        F4U hv; hv.f = *(const float4*)(hb + s * C);
        a0 = fma2(hv.u[0], dv2, a0);
        a1 = fma2(hv.u[1], dv2, a1);
    }
    float dn = dinv[n];
    float2 r01 = unpack2(a0), r23 = unpack2(a1);
    float4 b = *(const float4*)&bias[ch];
    float4 o;
    o.x = fmaxf(r01.x * dn + b.x, 0.f);
    o.y = fmaxf(r01.y * dn + b.y, 0.f);
    o.z = fmaxf(r23.x * dn + b.z, 0.f);
    o.w = fmaxf(r23.y * dn + b.w, 0.f);
    *(float4*)&out[n * C + ch] = o;
}

// ---------------- GAT: max + sum(exp), cache exp(e-m) ----------------
template<int H>
__global__ void gat_maxsum_kernel(const float* __restrict__ asrc, const float* __restrict__ adst,
                                  const int* __restrict__ rowptr, const int* __restrict__ csr,
                                  float* __restrict__ sArr, float* __restrict__ ex) {
    int warp = (blockIdx.x * blockDim.x + threadIdx.x) >> 5;
    int lane = threadIdx.x & 31;
    int n = warp;
    if (n >= NN) return;
    float ad[H];
#pragma unroll
    for (int q = 0; q < H / 4; q++) {
        float4 v = *(const float4*)&adst[n * H + 4 * q];
        ad[4 * q + 0] = v.x; ad[4 * q + 1] = v.y; ad[4 * q + 2] = v.z; ad[4 * q + 3] = v.w;
    }
    int r0 = rowptr[n], r1 = rowptr[n + 1];
    float mx[H];
#pragma unroll
    for (int hd = 0; hd < H; hd++) mx[hd] = -1e30f;
    for (int j = r0 + lane; j < r1; j += 32) {
        int s = csr[j];
        float as[H];
#pragma unroll
        for (int q = 0; q < H / 4; q++) {
            float4 v = *(const float4*)&asrc[s * H + 4 * q];
            as[4 * q + 0] = v.x; as[4 * q + 1] = v.y; as[4 * q + 2] = v.z; as[4 * q + 3] = v.w;
        }
#pragma unroll
        for (int hd = 0; hd < H; hd++) {
            float e = as[hd] + ad[hd];
            e = fmaxf(e, NEG_SLOPE * e);
            mx[hd] = fmaxf(mx[hd], e);
        }
    }
#pragma unroll
    for (int hd = 0; hd < H; hd++)
#pragma unroll
        for (int o = 16; o; o >>= 1) mx[hd] = fmaxf(mx[hd], __shfl_xor_sync(0xffffffffu, mx[hd], o));
    float sm[H];
#pragma unroll
    for (int hd = 0; hd < H; hd++) sm[hd] = 0.f;
    for (int j = r0 + lane; j < r1; j += 32) {
        int s = csr[j];
        float as[H];
#pragma unroll
        for (int q = 0; q < H / 4; q++) {
            float4 v = *(const float4*)&asrc[s * H + 4 * q];
            as[4 * q + 0] = v.x; as[4 * q + 1] = v.y; as[4 * q + 2] = v.z; as[4 * q + 3] = v.w;
        }
        float exv[H];
#pragma unroll
        for (int hd = 0; hd < H; hd++) {
            float e = as[hd] + ad[hd];
            e = fmaxf(e, NEG_SLOPE * e);
            float xv = __expf(e - mx[hd]);
            exv[hd] = xv;
            sm[hd] += xv;
        }
#pragma unroll
        for (int q = 0; q < H / 4; q++)
            *(float4*)&ex[(size_t)j * H + 4 * q] =
                make_float4(exv[4 * q + 0], exv[4 * q + 1], exv[4 * q + 2], exv[4 * q + 3]);
    }
#pragma unroll
    for (int hd = 0; hd < H; hd++)
#pragma unroll
        for (int o = 16; o; o >>= 1) sm[hd] += __shfl_xor_sync(0xffffffffu, sm[hd], o);
    if (lane == 0) {
#pragma unroll
        for (int hd = 0; hd < H; hd++) sArr[n * H + hd] = sm[hd];
    }
}

// ---------------- GAT aggregation: bf16 h gather ----------------
template<int H>
__global__ __launch_bounds__(128) void gat_agg_kernel(
        const __nv_bfloat16* __restrict__ h, const float* __restrict__ ex,
        const float* __restrict__ sArr, const int* __restrict__ rowptr,
        const int* __restrict__ csr, const float* __restrict__ bias,
        float* __restrict__ out) {
    constexpr int HC = H * 32;
    constexpr int TPN = HC / 4;
    constexpr int NPB = 128 / TPN;
    constexpr int CH = 32;
    __shared__ float2 al_sh[NPB][CH * H];
    __shared__ int off_sh[NPB][CH];
    __shared__ float inv_sh[NPB][H];
    __shared__ int r0_sh[NPB];
    __shared__ int cnt_sh[NPB];
    __shared__ int mx_sh;

    int tid = threadIdx.x;
    int g = tid / TPN, tg = tid % TPN;
    int n = blockIdx.x * NPB + g;
    if (tid == 0) mx_sh = 0;
    if (tg < H) inv_sh[g][tg] = 1.f / sArr[n * H + tg];
    if (tg == 0) {
        int r0 = rowptr[n], r1 = rowptr[n + 1];
        r0_sh[g] = r0;
        cnt_sh[g] = r1 - r0;
    }
    __syncthreads();
    if (tg == 0) atomicMax(&mx_sh, cnt_sh[g]);
    __syncthreads();
    int cnt = cnt_sh[g], r0 = r0_sh[g];
    int nch = (mx_sh + CH - 1) / CH;
    int ch0 = 4 * tg;
    int hd = tg >> 3;
    const __nv_bfloat16* hb = h + ch0;
    ull a0 = 0ull, a1 = 0ull;

    for (int c = 0; c < nch; c++) {
        int base = c * CH;
        int cc = min(CH, cnt - base);
#pragma unroll
        for (int it = 0; it < CH * H / TPN; it++) {
            int task = tg + it * TPN;
            int e = task / H;
            int hh = task - e * H;
            if (e < cc) {
                int j = r0 + base + e;
                float a = ex[(size_t)j * H + hh] * inv_sh[g][hh];
                al_sh[g][task] = make_float2(a, a);
                if (hh == 0) off_sh[g][e] = csr[j] * HC;
            }
        }
        __syncthreads();
        int e = 0;
        for (; e + 4 <= cc; e += 4) {
            int o0 = off_sh[g][e], o1 = off_sh[g][e + 1], o2 = off_sh[g][e + 2], o3 = off_sh[g][e + 3];
            F2U A0, A1, A2, A3;
            A0.f = al_sh[g][(e + 0) * H + hd];
            A1.f = al_sh[g][(e + 1) * H + hd];
            A2.f = al_sh[g][(e + 2) * H + hd];
            A3.f = al_sh[g][(e + 3) * H + hd];
            uint2 v0 = *(const uint2*)(hb + o0);
            uint2 v1 = *(const uint2*)(hb + o1);
            uint2 v2 = *(const uint2*)(hb + o2);
            uint2 v3 = *(const uint2*)(hb + o3);
            F2U f;
            f.f = __bfloat1622float2(*(__nv_bfloat162*)&v0.x); a0 = fma2(f.u, A0.u, a0);
            f.f = __bfloat1622float2(*(__nv_bfloat162*)&v0.y); a1 = fma2(f.u, A0.u, a1);
            f.f = __bfloat1622float2(*(__nv_bfloat162*)&v1.x); a0 = fma2(f.u, A1.u, a0);
            f.f = __bfloat1622float2(*(__nv_bfloat162*)&v1.y); a1 = fma2(f.u, A1.u, a1);
            f.f = __bfloat1622float2(*(__nv_bfloat162*)&v2.x); a0 = fma2(f.u, A2.u, a0);
            f.f = __bfloat1622float2(*(__nv_bfloat162*)&v2.y); a1 = fma2(f.u, A2.u, a1);
            f.f = __bfloat1622float2(*(__nv_bfloat162*)&v3.x); a0 = fma2(f.u, A3.u, a0);
            f.f = __bfloat1622float2(*(__nv_bfloat162*)&v3.y); a1 = fma2(f.u, A3.u, a1);
        }
        for (; e < cc; e++) {
            int o = off_sh[g][e];
            F2U A; A.f = al_sh[g][e * H + hd];
            uint2 v = *(const uint2*)(hb + o);
            F2U f;
            f.f = __bfloat1622float2(*(__nv_bfloat162*)&v.x); a0 = fma2(f.u, A.u, a0);
            f.f = __bfloat1622float2(*(__nv_bfloat162*)&v.y); a1 = fma2(f.u, A.u, a1);
        }
        __syncthreads();
    }
    float2 r01 = unpack2(a0), r23 = unpack2(a1);
    float4 b = *(const float4*)&bias[ch0];
    float4 o;
    o.x = fmaxf(r01.x + b.x, 0.f);
    o.y = fmaxf(r01.y + b.y, 0.f);
    o.z = fmaxf(r23.x + b.z, 0.f);
    o.w = fmaxf(r23.y + b.w, 0.f);
    *(float4*)&out[n * HC + ch0] = o;
}

// ---------------- pooling partials per layer ----------------
template<int NF4>
__global__ void pool_part_kernel(const float* __restrict__ src, int obase, int qy_total,
                                 const int* __restrict__ gstart, float* __restrict__ pool) {
    constexpr int SPB = 128 / NF4;
    int g = blockIdx.x;
    int q = blockIdx.y * SPB + threadIdx.x / NF4;
    int f = threadIdx.x % NF4;
    int slices = qy_total * SPB;
    int s = gstart[g], e = gstart[g + 1];
    int len = e - s;
    int n0 = s + (int)((long long)len * q / slices);
    int n1 = s + (int)((long long)len * (q + 1) / slices);
    ull a0 = 0ull, a1 = 0ull;
    int stride = NF4 * 4;
    for (int n = n0; n < n1; n++) {
        F4U v; v.f = *(const float4*)&src[(size_t)n * stride + 4 * f];
        a0 = add2(a0, v.u[0]);
        a1 = add2(a1, v.u[1]);
    }
    float2 r01 = unpack2(a0), r23 = unpack2(a1);
    float* dst = &pool[g * 432 + obase + 4 * f];
    atomicAdd(dst + 0, r01.x);
    atomicAdd(dst + 1, r01.y);
    atomicAdd(dst + 2, r23.x);
    atomicAdd(dst + 3, r23.y);
}

// ---------------- final MLP ----------------
__global__ void fc_kernel(const float* __restrict__ pool, const int* __restrict__ gstart,
                          const float* __restrict__ W1, const float* __restrict__ b1,
                          const float* __restrict__ W2, const float* __restrict__ b2,
                          float* __restrict__ out) {
    int g = blockIdx.x, t = threadIdx.x;
    __shared__ float xp[432];
    __shared__ float ws[4];
    float cntf = (float)(gstart[g + 1] - gstart[g]);
    float invc = 1.f / fmaxf(cntf, 1.f);
    for (int i = t; i < 432; i += 128) xp[i] = pool[g * 432 + i] * invc;
    __syncthreads();
    float acc = b1[t];
    for (int i = 0; i < 432; i++) acc += xp[i] * W1[i * 128 + t];
    acc = fmaxf(acc, 0.f);
    float v = acc * W2[t];
#pragma unroll
    for (int o = 16; o; o >>= 1) v += __shfl_xor_sync(0xffffffffu, v, o);
    if ((t & 31) == 0) ws[t >> 5] = v;
    __syncthreads();
    if (t == 0) out[g] = ws[0] + ws[1] + ws[2] + ws[3] + b2[0];
}

// ---------------- launch ----------------
extern "C" void kernel_launch(void* const* d_in, const int* in_sizes, int n_in,
                              void* d_out, int out_size) {
    const float* x    = (const float*)d_in[0];
    const int*   ei   = (const int*)d_in[1];
    const int*   batch= (const int*)d_in[2];
    const float* W1   = (const float*)d_in[3];
    const float* b1   = (const float*)d_in[4];
    const float* W2   = (const float*)d_in[5];
    const float* b2   = (const float*)d_in[6];
    const float* W3   = (const float*)d_in[7];
    const float* as3  = (const float*)d_in[8];
    const float* ad3  = (const float*)d_in[9];
    const float* b3   = (const float*)d_in[10];
    const float* W4   = (const float*)d_in[11];
    const float* as4  = (const float*)d_in[12];
    const float* ad4  = (const float*)d_in[13];
    const float* b4   = (const float*)d_in[14];
    const float* Wfc1 = (const float*)d_in[15];
    const float* bfc1 = (const float*)d_in[16];
    const float* Wfc2 = (const float*)d_in[17];
    const float* bfc2 = (const float*)d_in[18];
    float* out = (float*)d_out;

    static float *p_x1 = nullptr, *p_x2, *p_x3, *p_x4, *p_h, *p_asrc, *p_adst, *p_s,
                 *p_ex, *p_dinv, *p_pool;
    static __nv_bfloat16* p_hb;
    static int *p_counts, *p_bsum, *p_rowptr, *p_csr, *p_gstart;
    static cudaStream_t s1, s2;
    static cudaEvent_t evRoot, evG1, evX1, evX2, evX3, evX4, evFC;
    if (!p_x1) {
        cudaGetSymbolAddress((void**)&p_x1, g_x1);
        cudaGetSymbolAddress((void**)&p_x2, g_x2);
        cudaGetSymbolAddress((void**)&p_x3, g_x3);
        cudaGetSymbolAddress((void**)&p_x4, g_x4);
        cudaGetSymbolAddress((void**)&p_h, g_h);
        cudaGetSymbolAddress((void**)&p_hb, g_hb);
        cudaGetSymbolAddress((void**)&p_asrc, g_asrc);
        cudaGetSymbolAddress((void**)&p_adst, g_adst);
        cudaGetSymbolAddress((void**)&p_s, g_s);
        cudaGetSymbolAddress((void**)&p_ex, g_ex);
        cudaGetSymbolAddress((void**)&p_dinv, g_dinv);
        cudaGetSymbolAddress((void**)&p_pool, g_pool);
        cudaGetSymbolAddress((void**)&p_counts, g_counts);
        cudaGetSymbolAddress((void**)&p_bsum, g_bsum);
        cudaGetSymbolAddress((void**)&p_rowptr, g_rowptr);
        cudaGetSymbolAddress((void**)&p_csr, g_csr_src);
        cudaGetSymbolAddress((void**)&p_gstart, g_gstart);
        cudaStreamCreateWithFlags(&s1, cudaStreamNonBlocking);
        cudaStreamCreateWithFlags(&s2, cudaStreamNonBlocking);
        cudaEventCreateWithFlags(&evRoot, cudaEventDisableTiming);
        cudaEventCreateWithFlags(&evG1, cudaEventDisableTiming);
        cudaEventCreateWithFlags(&evX1, cudaEventDisableTiming);
        cudaEventCreateWithFlags(&evX2, cudaEventDisableTiming);
        cudaEventCreateWithFlags(&evX3, cudaEventDisableTiming);
        cudaEventCreateWithFlags(&evX4, cudaEventDisableTiming);
        cudaEventCreateWithFlags(&evFC, cudaEventDisableTiming);
    }

    // fork
    cudaEventRecord(evRoot, 0);
    cudaStreamWaitEvent(s1, evRoot, 0);
    cudaStreamWaitEvent(s2, evRoot, 0);

    // s0: CSR chain
    cudaMemsetAsync(p_counts, 0, NN * sizeof(int), 0);
    count_edges_kernel<<<(ETOT + 255) / 256, 256>>>(ei, p_counts);
    scan_reduce_kernel<<<RB, 1024>>>(p_counts, p_bsum);
    scan_offsets_kernel<<<1, 64>>>(p_bsum);
    scan_apply_kernel<<<RB, 1024>>>(p_counts, p_bsum, p_rowptr, p_dinv);
    fill_csr_kernel<<<(ETOT + 255) / 256, 256>>>(ei, p_counts, p_csr);

    // s1: gstart + pool init (independent)
    gstart_kernel<<<(NN + 255) / 256, 256, 0, s1>>>(batch, p_gstart);
    cudaMemsetAsync(p_pool, 0, GG * 432 * sizeof(float), s1);

    // s2: GEMM1 (independent of CSR)
    {
        dim3 b(4, 16), g((NN + 63) / 64, 1);
        gemm_small_kernel<128, 16><<<g, b, 0, s2>>>(x, W1, p_h);
        cudaEventRecord(evG1, s2);
    }

    // GCN layer 1 aggregate
    cudaStreamWaitEvent(0, evG1, 0);
    gcn_agg_kernel<16><<<(NN * 4 + 255) / 256, 256>>>(p_h, p_dinv, p_rowptr, p_csr, b1, p_x1);
    cudaEventRecord(evX1, 0);
    cudaStreamWaitEvent(s1, evX1, 0);
    pool_part_kernel<4><<<dim3(GG, 1), 128, 0, s1>>>(p_x1, 0, 1, p_gstart, p_pool);

    // GCN layer 2
    {
        dim3 b(8, 16), g((NN + 63) / 64, 1);
        gemm_small_kernel<16, 32><<<g, b>>>(p_x1, W2, p_h);
    }
    gcn_agg_kernel<32><<<(NN * 8 + 255) / 256, 256>>>(p_h, p_dinv, p_rowptr, p_csr, b2, p_x2);
    cudaEventRecord(evX2, 0);
    cudaStreamWaitEvent(s1, evX2, 0);
    pool_part_kernel<8><<<dim3(GG, 1), 128, 0, s1>>>(p_x2, 16, 1, p_gstart, p_pool);

    // GAT layer 3 (32 -> 4x32)
    {
        dim3 b(8, 16), g((NN + 127) / 128, 2);
        gemm_big_kernel<32, 128><<<g, b>>>(p_x2, W3, p_hb, as3, ad3, p_asrc, p_adst);
    }
    gat_maxsum_kernel<4><<<(NN * 32 + 255) / 256, 256>>>(p_asrc, p_adst, p_rowptr, p_csr, p_s, p_ex);
    gat_agg_kernel<4><<<NN / 4, 128>>>(p_hb, p_ex, p_s, p_rowptr, p_csr, b3, p_x3);
    cudaEventRecord(evX3, 0);
    cudaStreamWaitEvent(s1, evX3, 0);
    pool_part_kernel<32><<<dim3(GG, 2), 128, 0, s1>>>(p_x3, 48, 2, p_gstart, p_pool);

    // GAT layer 4 (128 -> 8x32)
    {
        dim3 b(8, 16), g((NN + 127) / 128, 4);
        gemm_big_kernel<128, 256><<<g, b>>>(p_x3, W4, p_hb, as4, ad4, p_asrc, p_adst);
    }
    gat_maxsum_kernel<8><<<(NN * 32 + 255) / 256, 256>>>(p_asrc, p_adst, p_rowptr, p_csr, p_s, p_ex);
    gat_agg_kernel<8><<<NN / 2, 128>>>(p_hb, p_ex, p_s, p_rowptr, p_csr, b4, p_x4);
    cudaEventRecord(evX4, 0);
    cudaStreamWaitEvent(s1, evX4, 0);
    pool_part_kernel<64><<<dim3(GG, 4), 128, 0, s1>>>(p_x4, 176, 4, p_gstart, p_pool);

    // FC on s1
    fc_kernel<<<GG, 128, 0, s1>>>(p_pool, p_gstart, Wfc1, bfc1, Wfc2, bfc2, out);
    cudaEventRecord(evFC, s1);
    cudaStreamWaitEvent(0, evFC, 0);
}

// round 7
// speedup vs baseline: 1.6622x; 1.1670x over previous
#include <cuda_runtime.h>
#include <cuda_bf16.h>
#include <cstdint>

#define NN 50000
#define EE 800000
#define ETOT (EE + NN)
#define GG 128
#define NEG_SLOPE 0.2f
#define RB 49   // ceil(NN/1024)

typedef unsigned long long ull;

union F4U { float4 f; ull u[2]; };
union F2U { float2 f; ull u; };

__device__ __forceinline__ ull fma2(ull a, ull b, ull c) {
    ull d; asm("fma.rn.f32x2 %0,%1,%2,%3;" : "=l"(d) : "l"(a), "l"(b), "l"(c)); return d;
}
__device__ __forceinline__ ull add2(ull a, ull b) {
    ull d; asm("add.rn.f32x2 %0,%1,%2;" : "=l"(d) : "l"(a), "l"(b)); return d;
}
__device__ __forceinline__ ull pack2(float x) {
    F2U t; t.f = make_float2(x, x); return t.u;
}
__device__ __forceinline__ float2 unpack2(ull v) { F2U t; t.u = v; return t.f; }

__device__ __forceinline__ uint32_t smem_u32(const void* p) {
    uint32_t a;
    asm("{ .reg .u64 t; cvta.to.shared.u64 t, %1; cvt.u32.u64 %0, t; }" : "=r"(a) : "l"(p));
    return a;
}
__device__ __forceinline__ void ldsm4(uint32_t& r0, uint32_t& r1, uint32_t& r2, uint32_t& r3,
                                      uint32_t addr) {
    asm volatile("ldmatrix.sync.aligned.m8n8.x4.shared.b16 {%0,%1,%2,%3}, [%4];"
                 : "=r"(r0), "=r"(r1), "=r"(r2), "=r"(r3) : "r"(addr));
}
__device__ __forceinline__ void mma16816(float* c, uint32_t a0, uint32_t a1, uint32_t a2,
                                         uint32_t a3, uint32_t b0, uint32_t b1) {
    asm volatile(
        "mma.sync.aligned.m16n8k16.row.col.f32.bf16.bf16.f32 "
        "{%0,%1,%2,%3},{%4,%5,%6,%7},{%8,%9},{%0,%1,%2,%3};"
        : "+f"(c[0]), "+f"(c[1]), "+f"(c[2]), "+f"(c[3])
        : "r"(a0), "r"(a1), "r"(a2), "r"(a3), "r"(b0), "r"(b1));
}

// ---------------- scratch ----------------
__device__ float g_x1[NN * 16];
__device__ float g_x2[NN * 32];
__device__ float g_x3[NN * 128];
__device__ float g_x4[NN * 256];
__device__ float g_h [NN * 32];
__device__ __nv_bfloat16 g_hb[NN * 256];
__device__ __nv_bfloat16 g_x2b[NN * 32];
__device__ __nv_bfloat16 g_x3b[NN * 128];
__device__ __nv_bfloat16 g_w3t[128 * 32];
__device__ __nv_bfloat16 g_w4t[256 * 128];
__device__ float g_asrc[NN * 8];
__device__ float g_adst[NN * 8];
__device__ float g_s[NN * 8];
__device__ float g_ex[(size_t)ETOT * 8];
__device__ float g_dinv[NN];
__device__ int   g_counts[NN];
__device__ int   g_bsum[RB];
__device__ int   g_rowptr[NN + 1];
__device__ int   g_csr_src[ETOT];
__device__ int   g_gstart[GG + 1];
__device__ float g_pool[GG * 432];

// ---------------- CSR build ----------------
__global__ void count_edges_kernel(const int* __restrict__ ei, int* __restrict__ counts) {
    int e = blockIdx.x * blockDim.x + threadIdx.x;
    if (e >= ETOT) return;
    int dst = (e < EE) ? ei[EE + e] : (e - EE);
    atomicAdd(&counts[dst], 1);
}

__global__ void scan_reduce_kernel(const int* __restrict__ counts, int* __restrict__ bsum) {
    __shared__ int ws[32];
    int i = blockIdx.x * 1024 + threadIdx.x;
    int v = (i < NN) ? counts[i] : 0;
    int lane = threadIdx.x & 31, w = threadIdx.x >> 5;
#pragma unroll
    for (int o = 16; o; o >>= 1) v += __shfl_xor_sync(0xffffffffu, v, o);
    if (lane == 0) ws[w] = v;
    __syncthreads();
    if (w == 0) {
        int s = ws[lane];
#pragma unroll
        for (int o = 16; o; o >>= 1) s += __shfl_xor_sync(0xffffffffu, s, o);
        if (lane == 0) bsum[blockIdx.x] = s;
    }
}

__global__ void scan_offsets_kernel(int* __restrict__ bsum) {
    __shared__ int ws[2];
    int t = threadIdx.x;
    int own = (t < RB) ? bsum[t] : 0;
    int v = own;
    int lane = t & 31, w = t >> 5;
#pragma unroll
    for (int o = 1; o < 32; o <<= 1) {
        int u = __shfl_up_sync(0xffffffffu, v, o);
        if (lane >= o) v += u;
    }
    if (lane == 31) ws[w] = v;
    __syncthreads();
    if (w == 1) v += ws[0];
    if (t < RB) bsum[t] = v - own;
}

__global__ void scan_apply_kernel(int* __restrict__ counts, const int* __restrict__ bsum,
                                  int* __restrict__ rowptr, float* __restrict__ dinv) {
    __shared__ int ws[32];
    int i = blockIdx.x * 1024 + threadIdx.x;
    int cnt = (i < NN) ? counts[i] : 0;
    int lane = threadIdx.x & 31, w = threadIdx.x >> 5;
    int v = cnt;
#pragma unroll
    for (int o = 1; o < 32; o <<= 1) {
        int u = __shfl_up_sync(0xffffffffu, v, o);
        if (lane >= o) v += u;
    }
    if (lane == 31) ws[w] = v;
    __syncthreads();
    if (w == 0) {
        int s = ws[lane];
#pragma unroll
        for (int o = 1; o < 32; o <<= 1) {
            int u = __shfl_up_sync(0xffffffffu, s, o);
            if (lane >= o) s += u;
        }
        ws[lane] = s;
    }
    __syncthreads();
    int incl = v + (w ? ws[w - 1] : 0) + bsum[blockIdx.x];
    if (i < NN) {
        rowptr[i + 1] = incl;
        counts[i] = incl - cnt;
        dinv[i] = rsqrtf((float)(cnt > 0 ? cnt : 1));
    }
    if (i == 0) rowptr[0] = 0;
}

__global__ void fill_csr_kernel(const int* __restrict__ ei, int* __restrict__ cursor,
                                int* __restrict__ csr) {
    int e = blockIdx.x * blockDim.x + threadIdx.x;
    if (e >= ETOT) return;
    int src, dst;
    if (e < EE) { src = ei[e]; dst = ei[EE + e]; }
    else        { src = dst = e - EE; }
    int pos = atomicAdd(&cursor[dst], 1);
    csr[pos] = src;
}

__global__ void gstart_kernel(const int* __restrict__ batch, int* __restrict__ gstart) {
    int n = blockIdx.x * blockDim.x + threadIdx.x;
    if (n >= NN) return;
    int b = batch[n];
    if (n == 0) { for (int g = 0; g <= b; g++) gstart[g] = 0; }
    else {
        int pb = batch[n - 1];
        for (int g = pb + 1; g <= b; g++) gstart[g] = n;
    }
    if (n == NN - 1) { for (int g = b + 1; g <= GG; g++) gstart[g] = NN; }
}

// ---- W transpose to bf16 [NOUT][KEL] ----
template<int KEL, int NOUT>
__global__ void wt_kernel(const float* __restrict__ W, __nv_bfloat16* __restrict__ Wt) {
    int idx = blockIdx.x * 256 + threadIdx.x;
    if (idx >= KEL * NOUT) return;
    int n = idx / KEL, k = idx % KEL;
    Wt[idx] = __float2bfloat16(W[k * NOUT + n]);
}

// ---------------- small GEMM (M=16/32) ----------------
template<int K, int M>
__global__ void gemm_small_kernel(const float* __restrict__ X, const float* __restrict__ W,
                                  float* __restrict__ Y) {
    constexpr int CT = M;
    constexpr int KC = (K < 64) ? K : 64;
    constexpr int TX = CT / 4;
    constexpr int NT = TX * 16;
    constexpr int RP = 68;
    __shared__ float Xs[KC * RP];
    __shared__ float Ws[KC * CT];
    int row0 = blockIdx.x * 64;
    int tid = threadIdx.y * TX + threadIdx.x;
    float acc[4][4] = {};
    for (int k0 = 0; k0 < K; k0 += KC) {
        for (int idx = tid; idx < 64 * KC; idx += NT) {
            int r = idx / KC, k = idx % KC;
            int gr = row0 + r;
            Xs[k * RP + r] = (gr < NN) ? X[gr * K + k0 + k] : 0.f;
        }
        for (int idx = tid; idx < KC * CT; idx += NT) {
            int k = idx / CT, c = idx % CT;
            Ws[k * CT + c] = W[(k0 + k) * M + c];
        }
        __syncthreads();
#pragma unroll 8
        for (int k = 0; k < KC; k++) {
            float4 xv = *(const float4*)&Xs[k * RP + 4 * threadIdx.y];
            float4 wv = *(const float4*)&Ws[k * CT + 4 * threadIdx.x];
            float xa[4] = {xv.x, xv.y, xv.z, xv.w};
            float wa[4] = {wv.x, wv.y, wv.z, wv.w};
#pragma unroll
            for (int i = 0; i < 4; i++)
#pragma unroll
                for (int j = 0; j < 4; j++)
                    acc[i][j] += xa[i] * wa[j];
        }
        __syncthreads();
    }
#pragma unroll
    for (int i = 0; i < 4; i++) {
        int r = row0 + 4 * threadIdx.y + i;
        if (r < NN) {
            float4 o = make_float4(acc[i][0], acc[i][1], acc[i][2], acc[i][3]);
            *(float4*)&Y[r * M + 4 * threadIdx.x] = o;
        }
    }
}

// ---------------- HMMA GEMM: h = X@W (bf16), fused attention coefficients ----------------
// 64 rows x NOUT per CTA; 8 warps = 4 row-groups x 2 col-halves; mma.m16n8k16 bf16.
template<int KEL, int NOUT>
__global__ __launch_bounds__(256) void gemm_mma_kernel(
        const __nv_bfloat16* __restrict__ Xb, const __nv_bfloat16* __restrict__ Wt,
        const float* __restrict__ att_s, const float* __restrict__ att_d,
        __nv_bfloat16* __restrict__ Yb, float* __restrict__ asrc, float* __restrict__ adst) {
    constexpr int H = NOUT / 32;
    constexpr int KP = KEL + 8;                 // padded row (elements)
    constexpr int KPB = KP * 2;                 // bytes
    constexpr int A_OFF = 0;
    constexpr int B_OFF = 64 * KPB;
    constexpr int ATT_OFF = B_OFF + NOUT * KPB;
    constexpr int AU = KEL / 8;                 // uint4 per row
    constexpr int NTILES = NOUT / 16;           // n8-tiles per warp (over NOUT/2 cols)

    extern __shared__ char smem[];
    uint32_t sb = smem_u32(smem);
    int tid = threadIdx.x, w = tid >> 5, lane = tid & 31;
    int row0 = blockIdx.x * 64;

    // A tile [64, KEL] bf16, padded rows
    for (int idx = tid; idx < 64 * AU; idx += 256) {
        int r = idx / AU, u = idx % AU;
        int gr = row0 + r;
        uint4 v = make_uint4(0, 0, 0, 0);
        if (gr < NN) v = *(const uint4*)&Xb[(size_t)gr * KEL + u * 8];
        *(uint4*)(smem + A_OFF + r * KPB + u * 16) = v;
    }
    // B tile: whole W^T [NOUT, KEL]
    for (int idx = tid; idx < NOUT * AU; idx += 256) {
        int r = idx / AU, u = idx % AU;
        *(uint4*)(smem + B_OFF + r * KPB + u * 16) = *(const uint4*)&Wt[r * KEL + u * 8];
    }
    float* att_sh = (float*)(smem + ATT_OFF);
    for (int idx = tid; idx < 2 * H * 32; idx += 256)
        att_sh[idx] = (idx < H * 32) ? att_s[idx] : att_d[idx - H * 32];
    __syncthreads();

    int wr = w >> 1, wc = w & 1;
    float acc[NTILES][4];
#pragma unroll
    for (int t = 0; t < NTILES; t++)
#pragma unroll
        for (int q = 0; q < 4; q++) acc[t][q] = 0.f;

    uint32_t aaddr = sb + A_OFF + (wr * 16 + (lane & 15)) * KPB + ((lane >> 4) << 4);
    uint32_t baddr = sb + B_OFF +
                     (wc * (NOUT / 2) + (lane & 7) + ((lane >> 4) << 3)) * KPB +
                     (((lane >> 3) & 1) << 4);
#pragma unroll
    for (int ks = 0; ks < KEL / 16; ks++) {
        uint32_t a0, a1, a2, a3;
        ldsm4(a0, a1, a2, a3, aaddr + ks * 32);
#pragma unroll
        for (int p = 0; p < NTILES / 2; p++) {
            uint32_t b0, b1, b2, b3;
            ldsm4(b0, b1, b2, b3, baddr + p * 16 * KPB + ks * 32);
            mma16816(acc[2 * p],     a0, a1, a2, a3, b0, b1);
            mma16816(acc[2 * p + 1], a0, a1, a2, a3, b2, b3);
        }
    }

    int g = lane >> 2;
    int r0g = row0 + wr * 16 + g;
    int r1g = r0g + 8;
    constexpr int HLOC = H / 2;
#pragma unroll
    for (int hh = 0; hh < HLOC; hh++) {
        int ghead = wc * HLOC + hh;
        float s0 = 0.f, d0 = 0.f, s1 = 0.f, d1 = 0.f;
#pragma unroll
        for (int t4 = 0; t4 < 4; t4++) {
            int t = hh * 4 + t4;
            int cih = t4 * 8 + (lane & 3) * 2;
            float aS0 = att_sh[ghead * 32 + cih];
            float aS1 = att_sh[ghead * 32 + cih + 1];
            float aD0 = att_sh[H * 32 + ghead * 32 + cih];
            float aD1 = att_sh[H * 32 + ghead * 32 + cih + 1];
            s0 += acc[t][0] * aS0 + acc[t][1] * aS1;
            d0 += acc[t][0] * aD0 + acc[t][1] * aD1;
            s1 += acc[t][2] * aS0 + acc[t][3] * aS1;
            d1 += acc[t][2] * aD0 + acc[t][3] * aD1;
        }
#pragma unroll
        for (int o = 1; o <= 2; o <<= 1) {
            s0 += __shfl_xor_sync(0xffffffffu, s0, o);
            d0 += __shfl_xor_sync(0xffffffffu, d0, o);
            s1 += __shfl_xor_sync(0xffffffffu, s1, o);
            d1 += __shfl_xor_sync(0xffffffffu, d1, o);
        }
        if ((lane & 3) == 0) {
            if (r0g < NN) { asrc[r0g * H + ghead] = s0; adst[r0g * H + ghead] = d0; }
            if (r1g < NN) { asrc[r1g * H + ghead] = s1; adst[r1g * H + ghead] = d1; }
        }
    }
    // bf16 h stores
#pragma unroll
    for (int t = 0; t < NTILES; t++) {
        int col = wc * (NOUT / 2) + t * 8 + (lane & 3) * 2;
        if (r0g < NN) {
            __nv_bfloat162 b2 = __float22bfloat162_rn(make_float2(acc[t][0], acc[t][1]));
            *(uint32_t*)&Yb[(size_t)r0g * NOUT + col] = *(uint32_t*)&b2;
        }
        if (r1g < NN) {
            __nv_bfloat162 b2 = __float22bfloat162_rn(make_float2(acc[t][2], acc[t][3]));
            *(uint32_t*)&Yb[(size_t)r1g * NOUT + col] = *(uint32_t*)&b2;
        }
    }
}

// ---------------- GCN aggregate (optional bf16 copy out) ----------------
template<int C>
__global__ void gcn_agg_kernel(const float* __restrict__ h, const float* __restrict__ dinv,
                               const int* __restrict__ rowptr, const int* __restrict__ csr,
                               const float* __restrict__ bias, float* __restrict__ out,
                               __nv_bfloat16* __restrict__ outb) {
    constexpr int TPN = C / 4;
    int gtid = blockIdx.x * blockDim.x + threadIdx.x;
    int n = gtid / TPN;
    int ch = 4 * (gtid % TPN);
    if (n >= NN) return;
    int r0 = rowptr[n], r1 = rowptr[n + 1];
    const float* hb = h + ch;
    ull a0 = 0ull, a1 = 0ull;
    for (int j = r0; j < r1; j++) {
        int s = csr[j];
        ull dv2 = pack2(dinv[s]);
        F4U hv; hv.f = *(const float4*)(hb + s * C);
        a0 = fma2(hv.u[0], dv2, a0);
        a1 = fma2(hv.u[1], dv2, a1);
    }
    float dn = dinv[n];
    float2 r01 = unpack2(a0), r23 = unpack2(a1);
    float4 b = *(const float4*)&bias[ch];
    float4 o;
    o.x = fmaxf(r01.x * dn + b.x, 0.f);
    o.y = fmaxf(r01.y * dn + b.y, 0.f);
    o.z = fmaxf(r23.x * dn + b.z, 0.f);
    o.w = fmaxf(r23.y * dn + b.w, 0.f);
    *(float4*)&out[n * C + ch] = o;
    if (outb) {
        __nv_bfloat162 p0 = __float22bfloat162_rn(make_float2(o.x, o.y));
        __nv_bfloat162 p1 = __float22bfloat162_rn(make_float2(o.z, o.w));
        uint2 u; u.x = *(uint32_t*)&p0; u.y = *(uint32_t*)&p1;
        *(uint2*)&outb[n * C + ch] = u;
    }
}

// ---------------- GAT: max + sum(exp), cache exp(e-m) ----------------
template<int H>
__global__ void gat_maxsum_kernel(const float* __restrict__ asrc, const float* __restrict__ adst,
                                  const int* __restrict__ rowptr, const int* __restrict__ csr,
                                  float* __restrict__ sArr, float* __restrict__ ex) {
    int warp = (blockIdx.x * blockDim.x + threadIdx.x) >> 5;
    int lane = threadIdx.x & 31;
    int n = warp;
    if (n >= NN) return;
    float ad[H];
#pragma unroll
    for (int q = 0; q < H / 4; q++) {
        float4 v = *(const float4*)&adst[n * H + 4 * q];
        ad[4 * q + 0] = v.x; ad[4 * q + 1] = v.y; ad[4 * q + 2] = v.z; ad[4 * q + 3] = v.w;
    }
    int r0 = rowptr[n], r1 = rowptr[n + 1];
    float mx[H];
#pragma unroll
    for (int hd = 0; hd < H; hd++) mx[hd] = -1e30f;
    for (int j = r0 + lane; j < r1; j += 32) {
        int s = csr[j];
        float as[H];
#pragma unroll
        for (int q = 0; q < H / 4; q++) {
            float4 v = *(const float4*)&asrc[s * H + 4 * q];
            as[4 * q + 0] = v.x; as[4 * q + 1] = v.y; as[4 * q + 2] = v.z; as[4 * q + 3] = v.w;
        }
#pragma unroll
        for (int hd = 0; hd < H; hd++) {
            float e = as[hd] + ad[hd];
            e = fmaxf(e, NEG_SLOPE * e);
            mx[hd] = fmaxf(mx[hd], e);
        }
    }
#pragma unroll
    for (int hd = 0; hd < H; hd++)
#pragma unroll
        for (int o = 16; o; o >>= 1) mx[hd] = fmaxf(mx[hd], __shfl_xor_sync(0xffffffffu, mx[hd], o));
    float sm[H];
#pragma unroll
    for (int hd = 0; hd < H; hd++) sm[hd] = 0.f;
    for (int j = r0 + lane; j < r1; j += 32) {
        int s = csr[j];
        float as[H];
#pragma unroll
        for (int q = 0; q < H / 4; q++) {
            float4 v = *(const float4*)&asrc[s * H + 4 * q];
            as[4 * q + 0] = v.x; as[4 * q + 1] = v.y; as[4 * q + 2] = v.z; as[4 * q + 3] = v.w;
        }
        float exv[H];
#pragma unroll
        for (int hd = 0; hd < H; hd++) {
            float e = as[hd] + ad[hd];
            e = fmaxf(e, NEG_SLOPE * e);
            float xv = __expf(e - mx[hd]);
            exv[hd] = xv;
            sm[hd] += xv;
        }
#pragma unroll
        for (int q = 0; q < H / 4; q++)
            *(float4*)&ex[(size_t)j * H + 4 * q] =
                make_float4(exv[4 * q + 0], exv[4 * q + 1], exv[4 * q + 2], exv[4 * q + 3]);
    }
#pragma unroll
    for (int hd = 0; hd < H; hd++)
#pragma unroll
        for (int o = 16; o; o >>= 1) sm[hd] += __shfl_xor_sync(0xffffffffu, sm[hd], o);
    if (lane == 0) {
#pragma unroll
        for (int hd = 0; hd < H; hd++) sArr[n * H + hd] = sm[hd];
    }
}

// ---------------- GAT aggregation: bf16 h gather (optional bf16 copy out) ----------------
template<int H>
__global__ __launch_bounds__(128) void gat_agg_kernel(
        const __nv_bfloat16* __restrict__ h, const float* __restrict__ ex,
        const float* __restrict__ sArr, const int* __restrict__ rowptr,
        const int* __restrict__ csr, const float* __restrict__ bias,
        float* __restrict__ out, __nv_bfloat16* __restrict__ outb) {
    constexpr int HC = H * 32;
    constexpr int TPN = HC / 4;
    constexpr int NPB = 128 / TPN;
    constexpr int CH = 32;
    __shared__ float2 al_sh[NPB][CH * H];
    __shared__ int off_sh[NPB][CH];
    __shared__ float inv_sh[NPB][H];
    __shared__ int r0_sh[NPB];
    __shared__ int cnt_sh[NPB];
    __shared__ int mx_sh;

    int tid = threadIdx.x;
    int g = tid / TPN, tg = tid % TPN;
    int n = blockIdx.x * NPB + g;
    if (tid == 0) mx_sh = 0;
    if (tg < H) inv_sh[g][tg] = 1.f / sArr[n * H + tg];
    if (tg == 0) {
        int r0 = rowptr[n], r1 = rowptr[n + 1];
        r0_sh[g] = r0;
        cnt_sh[g] = r1 - r0;
    }
    __syncthreads();
    if (tg == 0) atomicMax(&mx_sh, cnt_sh[g]);
    __syncthreads();
    int cnt = cnt_sh[g], r0 = r0_sh[g];
    int nch = (mx_sh + CH - 1) / CH;
    int ch0 = 4 * tg;
    int hd = tg >> 3;
    const __nv_bfloat16* hb = h + ch0;
    ull a0 = 0ull, a1 = 0ull;

    for (int c = 0; c < nch; c++) {
        int base = c * CH;
        int cc = min(CH, cnt - base);
#pragma unroll
        for (int it = 0; it < CH * H / TPN; it++) {
            int task = tg + it * TPN;
            int e = task / H;
            int hh = task - e * H;
            if (e < cc) {
                int j = r0 + base + e;
                float a = ex[(size_t)j * H + hh] * inv_sh[g][hh];
                al_sh[g][task] = make_float2(a, a);
                if (hh == 0) off_sh[g][e] = csr[j] * HC;
            }
        }
        __syncthreads();
        int e = 0;
        for (; e + 4 <= cc; e += 4) {
            int o0 = off_sh[g][e], o1 = off_sh[g][e + 1], o2 = off_sh[g][e + 2], o3 = off_sh[g][e + 3];
            F2U A0, A1, A2, A3;
            A0.f = al_sh[g][(e + 0) * H + hd];
            A1.f = al_sh[g][(e + 1) * H + hd];
            A2.f = al_sh[g][(e + 2) * H + hd];
            A3.f = al_sh[g][(e + 3) * H + hd];
            uint2 v0 = *(const uint2*)(hb + o0);
            uint2 v1 = *(const uint2*)(hb + o1);
            uint2 v2 = *(const uint2*)(hb + o2);
            uint2 v3 = *(const uint2*)(hb + o3);
            F2U f;
            f.f = __bfloat1622float2(*(__nv_bfloat162*)&v0.x); a0 = fma2(f.u, A0.u, a0);
            f.f = __bfloat1622float2(*(__nv_bfloat162*)&v0.y); a1 = fma2(f.u, A0.u, a1);
            f.f = __bfloat1622float2(*(__nv_bfloat162*)&v1.x); a0 = fma2(f.u, A1.u, a0);
            f.f = __bfloat1622float2(*(__nv_bfloat162*)&v1.y); a1 = fma2(f.u, A1.u, a1);
            f.f = __bfloat1622float2(*(__nv_bfloat162*)&v2.x); a0 = fma2(f.u, A2.u, a0);
            f.f = __bfloat1622float2(*(__nv_bfloat162*)&v2.y); a1 = fma2(f.u, A2.u, a1);
            f.f = __bfloat1622float2(*(__nv_bfloat162*)&v3.x); a0 = fma2(f.u, A3.u, a0);
            f.f = __bfloat1622float2(*(__nv_bfloat162*)&v3.y); a1 = fma2(f.u, A3.u, a1);
        }
        for (; e < cc; e++) {
            int o = off_sh[g][e];
            F2U A; A.f = al_sh[g][e * H + hd];
            uint2 v = *(const uint2*)(hb + o);
            F2U f;
            f.f = __bfloat1622float2(*(__nv_bfloat162*)&v.x); a0 = fma2(f.u, A.u, a0);
            f.f = __bfloat1622float2(*(__nv_bfloat162*)&v.y); a1 = fma2(f.u, A.u, a1);
        }
        __syncthreads();
    }
    float2 r01 = unpack2(a0), r23 = unpack2(a1);
    float4 b = *(const float4*)&bias[ch0];
    float4 o;
    o.x = fmaxf(r01.x + b.x, 0.f);
    o.y = fmaxf(r01.y + b.y, 0.f);
    o.z = fmaxf(r23.x + b.z, 0.f);
    o.w = fmaxf(r23.y + b.w, 0.f);
    *(float4*)&out[n * HC + ch0] = o;
    if (outb) {
        __nv_bfloat162 p0 = __float22bfloat162_rn(make_float2(o.x, o.y));
        __nv_bfloat162 p1 = __float22bfloat162_rn(make_float2(o.z, o.w));
        uint2 u; u.x = *(uint32_t*)&p0; u.y = *(uint32_t*)&p1;
        *(uint2*)&outb[n * HC + ch0] = u;
    }
}

// ---------------- pooling partials per layer ----------------
template<int NF4>
__global__ void pool_part_kernel(const float* __restrict__ src, int obase, int qy_total,
                                 const int* __restrict__ gstart, float* __restrict__ pool) {
    constexpr int SPB = 128 / NF4;
    int g = blockIdx.x;
    int q = blockIdx.y * SPB + threadIdx.x / NF4;
    int f = threadIdx.x % NF4;
    int slices = qy_total * SPB;
    int s = gstart[g], e = gstart[g + 1];
    int len = e - s;
    int n0 = s + (int)((long long)len * q / slices);
    int n1 = s + (int)((long long)len * (q + 1) / slices);
    ull a0 = 0ull, a1 = 0ull;
    int stride = NF4 * 4;
    for (int n = n0; n < n1; n++) {
        F4U v; v.f = *(const float4*)&src[(size_t)n * stride + 4 * f];
        a0 = add2(a0, v.u[0]);
        a1 = add2(a1, v.u[1]);
    }
    float2 r01 = unpack2(a0), r23 = unpack2(a1);
    float* dst = &pool[g * 432 + obase + 4 * f];
    atomicAdd(dst + 0, r01.x);
    atomicAdd(dst + 1, r01.y);
    atomicAdd(dst + 2, r23.x);
    atomicAdd(dst + 3, r23.y);
}

// ---------------- final MLP ----------------
__global__ void fc_kernel(const float* __restrict__ pool, const int* __restrict__ gstart,
                          const float* __restrict__ W1, const float* __restrict__ b1,
                          const float* __restrict__ W2, const float* __restrict__ b2,
                          float* __restrict__ out) {
    int g = blockIdx.x, t = threadIdx.x;
    __shared__ float xp[432];
    __shared__ float ws[4];
    float cntf = (float)(gstart[g + 1] - gstart[g]);
    float invc = 1.f / fmaxf(cntf, 1.f);
    for (int i = t; i < 432; i += 128) xp[i] = pool[g * 432 + i] * invc;
    __syncthreads();
    float acc = b1[t];
    for (int i = 0; i < 432; i++) acc += xp[i] * W1[i * 128 + t];
    acc = fmaxf(acc, 0.f);
    float v = acc * W2[t];
#pragma unroll
    for (int o = 16; o; o >>= 1) v += __shfl_xor_sync(0xffffffffu, v, o);
    if ((t & 31) == 0) ws[t >> 5] = v;
    __syncthreads();
    if (t == 0) out[g] = ws[0] + ws[1] + ws[2] + ws[3] + b2[0];
}

// ---------------- launch ----------------
extern "C" void kernel_launch(void* const* d_in, const int* in_sizes, int n_in,
                              void* d_out, int out_size) {
    const float* x    = (const float*)d_in[0];
    const int*   ei   = (const int*)d_in[1];
    const int*   batch= (const int*)d_in[2];
    const float* W1   = (const float*)d_in[3];
    const float* b1   = (const float*)d_in[4];
    const float* W2   = (const float*)d_in[5];
    const float* b2   = (const float*)d_in[6];
    const float* W3   = (const float*)d_in[7];
    const float* as3  = (const float*)d_in[8];
    const float* ad3  = (const float*)d_in[9];
    const float* b3   = (const float*)d_in[10];
    const float* W4   = (const float*)d_in[11];
    const float* as4  = (const float*)d_in[12];
    const float* ad4  = (const float*)d_in[13];
    const float* b4   = (const float*)d_in[14];
    const float* Wfc1 = (const float*)d_in[15];
    const float* bfc1 = (const float*)d_in[16];
    const float* Wfc2 = (const float*)d_in[17];
    const float* bfc2 = (const float*)d_in[18];
    float* out = (float*)d_out;

    // smem sizes: A 64*(K+8)*2 + B NOUT*(K+8)*2 + att 2*H*32*4
    constexpr int SMEM3 = 64 * 80 + 128 * 80 + 2 * 4 * 32 * 4;     // 16384
    constexpr int SMEM4 = 64 * 272 + 256 * 272 + 2 * 8 * 32 * 4;   // 89088

    static float *p_x1 = nullptr, *p_x2, *p_x3, *p_x4, *p_h, *p_asrc, *p_adst, *p_s,
                 *p_ex, *p_dinv, *p_pool;
    static __nv_bfloat16 *p_hb, *p_x2b, *p_x3b, *p_w3t, *p_w4t;
    static int *p_counts, *p_bsum, *p_rowptr, *p_csr, *p_gstart;
    static cudaStream_t s1, s2;
    static cudaEvent_t evRoot, evG1, evW, evX1, evX2, evX3, evX4, evFC;
    if (!p_x1) {
        cudaGetSymbolAddress((void**)&p_x1, g_x1);
        cudaGetSymbolAddress((void**)&p_x2, g_x2);
        cudaGetSymbolAddress((void**)&p_x3, g_x3);
        cudaGetSymbolAddress((void**)&p_x4, g_x4);
        cudaGetSymbolAddress((void**)&p_h, g_h);
        cudaGetSymbolAddress((void**)&p_hb, g_hb);
        cudaGetSymbolAddress((void**)&p_x2b, g_x2b);
        cudaGetSymbolAddress((void**)&p_x3b, g_x3b);
        cudaGetSymbolAddress((void**)&p_w3t, g_w3t);
        cudaGetSymbolAddress((void**)&p_w4t, g_w4t);
        cudaGetSymbolAddress((void**)&p_asrc, g_asrc);
        cudaGetSymbolAddress((void**)&p_adst, g_adst);
        cudaGetSymbolAddress((void**)&p_s, g_s);
        cudaGetSymbolAddress((void**)&p_ex, g_ex);
        cudaGetSymbolAddress((void**)&p_dinv, g_dinv);
        cudaGetSymbolAddress((void**)&p_pool, g_pool);
        cudaGetSymbolAddress((void**)&p_counts, g_counts);
        cudaGetSymbolAddress((void**)&p_bsum, g_bsum);
        cudaGetSymbolAddress((void**)&p_rowptr, g_rowptr);
        cudaGetSymbolAddress((void**)&p_csr, g_csr_src);
        cudaGetSymbolAddress((void**)&p_gstart, g_gstart);
        cudaStreamCreateWithFlags(&s1, cudaStreamNonBlocking);
        cudaStreamCreateWithFlags(&s2, cudaStreamNonBlocking);
        cudaEventCreateWithFlags(&evRoot, cudaEventDisableTiming);
        cudaEventCreateWithFlags(&evG1, cudaEventDisableTiming);
        cudaEventCreateWithFlags(&evW, cudaEventDisableTiming);
        cudaEventCreateWithFlags(&evX1, cudaEventDisableTiming);
        cudaEventCreateWithFlags(&evX2, cudaEventDisableTiming);
        cudaEventCreateWithFlags(&evX3, cudaEventDisableTiming);
        cudaEventCreateWithFlags(&evX4, cudaEventDisableTiming);
        cudaEventCreateWithFlags(&evFC, cudaEventDisableTiming);
        cudaFuncSetAttribute((const void*)gemm_mma_kernel<32, 128>,
                             cudaFuncAttributeMaxDynamicSharedMemorySize, SMEM3);
        cudaFuncSetAttribute((const void*)gemm_mma_kernel<128, 256>,
                             cudaFuncAttributeMaxDynamicSharedMemorySize, SMEM4);
    }

    // fork
    cudaEventRecord(evRoot, 0);
    cudaStreamWaitEvent(s1, evRoot, 0);
    cudaStreamWaitEvent(s2, evRoot, 0);

    // s0: CSR chain
    cudaMemsetAsync(p_counts, 0, NN * sizeof(int), 0);
    count_edges_kernel<<<(ETOT + 255) / 256, 256>>>(ei, p_counts);
    scan_reduce_kernel<<<RB, 1024>>>(p_counts, p_bsum);
    scan_offsets_kernel<<<1, 64>>>(p_bsum);
    scan_apply_kernel<<<RB, 1024>>>(p_counts, p_bsum, p_rowptr, p_dinv);
    fill_csr_kernel<<<(ETOT + 255) / 256, 256>>>(ei, p_counts, p_csr);

    // s1: gstart + pool init + W transposes (independent)
    gstart_kernel<<<(NN + 255) / 256, 256, 0, s1>>>(batch, p_gstart);
    cudaMemsetAsync(p_pool, 0, GG * 432 * sizeof(float), s1);
    wt_kernel<32, 128><<<(128 * 32 + 255) / 256, 256, 0, s1>>>(W3, p_w3t);
    wt_kernel<128, 256><<<(256 * 128 + 255) / 256, 256, 0, s1>>>(W4, p_w4t);
    cudaEventRecord(evW, s1);

    // s2: GEMM1 (independent of CSR)
    {
        dim3 b(4, 16), g((NN + 63) / 64, 1);
        gemm_small_kernel<128, 16><<<g, b, 0, s2>>>(x, W1, p_h);
        cudaEventRecord(evG1, s2);
    }

    // GCN layer 1 aggregate
    cudaStreamWaitEvent(0, evG1, 0);
    gcn_agg_kernel<16><<<(NN * 4 + 255) / 256, 256>>>(p_h, p_dinv, p_rowptr, p_csr, b1, p_x1, nullptr);
    cudaEventRecord(evX1, 0);
    cudaStreamWaitEvent(s1, evX1, 0);
    pool_part_kernel<4><<<dim3(GG, 1), 128, 0, s1>>>(p_x1, 0, 1, p_gstart, p_pool);

    // GCN layer 2
    {
        dim3 b(8, 16), g((NN + 63) / 64, 1);
        gemm_small_kernel<16, 32><<<g, b>>>(p_x1, W2, p_h);
    }
    gcn_agg_kernel<32><<<(NN * 8 + 255) / 256, 256>>>(p_h, p_dinv, p_rowptr, p_csr, b2, p_x2, p_x2b);
    cudaEventRecord(evX2, 0);
    cudaStreamWaitEvent(s1, evX2, 0);
    pool_part_kernel<8><<<dim3(GG, 1), 128, 0, s1>>>(p_x2, 16, 1, p_gstart, p_pool);

    // GAT layer 3 (32 -> 4x32), HMMA
    cudaStreamWaitEvent(0, evW, 0);
    gemm_mma_kernel<32, 128><<<(NN + 63) / 64, 256, SMEM3>>>(p_x2b, p_w3t, as3, ad3,
                                                             p_hb, p_asrc, p_adst);
    gat_maxsum_kernel<4><<<(NN * 32 + 255) / 256, 256>>>(p_asrc, p_adst, p_rowptr, p_csr, p_s, p_ex);
    gat_agg_kernel<4><<<NN / 4, 128>>>(p_hb, p_ex, p_s, p_rowptr, p_csr, b3, p_x3, p_x3b);
    cudaEventRecord(evX3, 0);
    cudaStreamWaitEvent(s1, evX3, 0);
    pool_part_kernel<32><<<dim3(GG, 2), 128, 0, s1>>>(p_x3, 48, 2, p_gstart, p_pool);

    // GAT layer 4 (128 -> 8x32), HMMA
    gemm_mma_kernel<128, 256><<<(NN + 63) / 64, 256, SMEM4>>>(p_x3b, p_w4t, as4, ad4,
                                                              p_hb, p_asrc, p_adst);
    gat_maxsum_kernel<8><<<(NN * 32 + 255) / 256, 256>>>(p_asrc, p_adst, p_rowptr, p_csr, p_s, p_ex);
    gat_agg_kernel<8><<<NN / 2, 128>>>(p_hb, p_ex, p_s, p_rowptr, p_csr, b4, p_x4, nullptr);
    cudaEventRecord(evX4, 0);
    cudaStreamWaitEvent(s1, evX4, 0);
    pool_part_kernel<64><<<dim3(GG, 4), 128, 0, s1>>>(p_x4, 176, 4, p_gstart, p_pool);

    // FC on s1
    fc_kernel<<<GG, 128, 0, s1>>>(p_pool, p_gstart, Wfc1, bfc1, Wfc2, bfc2, out);
    cudaEventRecord(evFC, s1);
    cudaStreamWaitEvent(0, evFC, 0);
}